// round 1
// baseline (speedup 1.0000x reference)
#include <cuda_runtime.h>
#include <cuda_bf16.h>
#include <math.h>

// Problem constants
#define BB   64
#define CC   64
#define HH   256
#define LL   64
#define PP   32
#define NREAL 2047
#define NN   2048

// ---------------- scratch (static device memory; no allocs allowed) --------
__device__ float  g_xt0 [(size_t)BB * NN * CC];    // transposed input [B][N][C]   (32 MB)
__device__ float  g_out1[(size_t)BB * NN * HH];    // conv1 out / later MLP1 h     (128 MB)
__device__ float  g_out2[(size_t)BB * NN * HH];    // conv2 out                    (128 MB)
__device__ float  g_w1p [3 * CC * HH];             // conv1_w repacked [3C][H]
__device__ float  g_w2p [3 * HH * HH];             // conv2_w repacked [3H][H]
__device__ double g_stats[2][BB][2];               // [stage][b][sum, sumsq]
__device__ float  g_norm [2][BB][2];               // [stage][b][mean, istd]

// ---------------- init: zero stats and node-0 rows --------------------------
__global__ void k_init() {
    int t = blockIdx.x * blockDim.x + threadIdx.x;
    if (t < 2 * BB * 2) ((double*)g_stats)[t] = 0.0;
    // zero row 0 (node 0) of out1/out2 for every batch: 64*256 floats each
    for (int i = t; i < BB * HH; i += gridDim.x * blockDim.x) {
        int b = i >> 8, h = i & 255;
        g_out1[(size_t)b * NN * HH + h] = 0.f;
        g_out2[(size_t)b * NN * HH + h] = 0.f;
    }
}

// ---------------- transpose node_feats [B,C,N] -> [B,N,C] -------------------
__global__ void k_transpose(const float* __restrict__ x) {
    __shared__ float tile[32][33];
    int b  = blockIdx.z;
    int n0 = blockIdx.x * 32;
    int c0 = blockIdx.y * 32;
    int tx = threadIdx.x, ty = threadIdx.y;
    tile[ty][tx] = x[((size_t)b * CC + c0 + ty) * NN + n0 + tx];
    __syncthreads();
    g_xt0[((size_t)b * NN + n0 + ty) * CC + c0 + tx] = tile[tx][ty];
}

// ---------------- repack conv weights: wp[(j*Cin+c)*H + h] = w[h][c][j] -----
__global__ void k_repack(const float* __restrict__ w1, const float* __restrict__ w2) {
    int t = blockIdx.x * blockDim.x + threadIdx.x;
    int stride = gridDim.x * blockDim.x;
    for (int i = t; i < 3 * CC * HH; i += stride) {
        int h = i & 255, k = i >> 8;          // k < 192
        int j = k >> 6, c = k & 63;
        g_w1p[i] = w1[(h * CC + c) * 3 + j];
    }
    for (int i = t; i < 3 * HH * HH; i += stride) {
        int h = i & 255, k = i >> 8;          // k < 768
        int j = k >> 8, c = k & 255;
        g_w2p[i] = w2[(h * HH + c) * 3 + j];
    }
}

// ---------------- gather-conv GEMM ------------------------------------------
// STAGE 0: xt0 -> out1 (Cin=64, raw gather)
// STAGE 1: out1 -> out2 (Cin=256, gather with norm1+relu applied on load)
// Block: 256 thr, tile = 64 nodes x 128 h. Thread: 8 nodes x 4 h.
template <int CIN, int STAGE>
__global__ void __launch_bounds__(256) k_conv(const float* __restrict__ bias,
                                              const int* __restrict__ children) {
    constexpr int K = 3 * CIN;
    const float* __restrict__ src = (STAGE == 0) ? g_xt0 : g_out1;
    const float* __restrict__ wp  = (STAGE == 0) ? g_w1p : g_w2p;
    float* __restrict__ dst       = (STAGE == 0) ? g_out1 : g_out2;

    const int b    = blockIdx.z;
    const int ht0  = blockIdx.y * 128;
    const int nt0  = 1 + blockIdx.x * 64;     // global node base (skip node 0)
    const int tid  = threadIdx.x;
    const int lane = tid & 31, warp = tid >> 5;

    __shared__ int   sidx[64 * 3];
    __shared__ float Asm[64][33];
    __shared__ float Wsm[32][128];
    __shared__ float rs[8], rss[8];

    float mean = 0.f, istd = 1.f;
    if (STAGE == 1) { mean = g_norm[0][b][0]; istd = g_norm[0][b][1]; }

    if (tid < 192) {
        int n = tid / 3, j = tid - n * 3;
        int gn = nt0 + n;
        sidx[tid] = (gn < NN) ? children[b * (3 * NREAL) + (gn - 1) * 3 + j] : 0;
    }

    float acc[8][4];
#pragma unroll
    for (int r = 0; r < 8; r++)
#pragma unroll
        for (int q = 0; q < 4; q++) acc[r][q] = 0.f;

    const float* srcb = src + (size_t)b * NN * CIN;

    for (int k0 = 0; k0 < K; k0 += 32) {
        __syncthreads();
        const int j  = k0 / CIN;
        const int c0 = k0 - j * CIN;
        // gather tile: warp w loads nodes [8w, 8w+8), 32 contiguous channels each
#pragma unroll
        for (int r = 0; r < 8; r++) {
            int n   = warp * 8 + r;
            int idx = sidx[n * 3 + j];
            float v = srcb[(size_t)idx * CIN + c0 + lane];
            if (STAGE == 1) v = fmaxf((v - mean) * istd, 0.f);
            Asm[n][lane] = v;
        }
        // weight tile [32 k x 128 h], coalesced
#pragma unroll
        for (int i = 0; i < 16; i++) {
            int li = tid + i * 256;
            int kk = li >> 7, hh = li & 127;
            Wsm[kk][hh] = wp[(k0 + kk) * HH + ht0 + hh];
        }
        __syncthreads();
#pragma unroll
        for (int kk = 0; kk < 32; kk++) {
            float4 w4 = *(const float4*)&Wsm[kk][lane * 4];
#pragma unroll
            for (int r = 0; r < 8; r++) {
                float a = Asm[warp * 8 + r][kk];
                acc[r][0] = fmaf(a, w4.x, acc[r][0]);
                acc[r][1] = fmaf(a, w4.y, acc[r][1]);
                acc[r][2] = fmaf(a, w4.z, acc[r][2]);
                acc[r][3] = fmaf(a, w4.w, acc[r][3]);
            }
        }
    }

    float4 bv = *(const float4*)&bias[ht0 + lane * 4];
    float s = 0.f, ss = 0.f;
#pragma unroll
    for (int r = 0; r < 8; r++) {
        int gn = nt0 + warp * 8 + r;
        if (gn < NN) {
            float4 o;
            o.x = acc[r][0] + bv.x; o.y = acc[r][1] + bv.y;
            o.z = acc[r][2] + bv.z; o.w = acc[r][3] + bv.w;
            *(float4*)&dst[((size_t)b * NN + gn) * HH + ht0 + lane * 4] = o;
            s  += o.x + o.y + o.z + o.w;
            ss += o.x * o.x + o.y * o.y + o.z * o.z + o.w * o.w;
        }
    }
    // block-reduce stats, two double atomics per block
#pragma unroll
    for (int off = 16; off > 0; off >>= 1) {
        s  += __shfl_down_sync(0xffffffffu, s,  off);
        ss += __shfl_down_sync(0xffffffffu, ss, off);
    }
    if (lane == 0) { rs[warp] = s; rss[warp] = ss; }
    __syncthreads();
    if (tid == 0) {
        float S = 0.f, SS = 0.f;
#pragma unroll
        for (int w = 0; w < 8; w++) { S += rs[w]; SS += rss[w]; }
        atomicAdd(&g_stats[STAGE][b][0], (double)S);
        atomicAdd(&g_stats[STAGE][b][1], (double)SS);
    }
}

// ---------------- finalize norm stats ---------------------------------------
__global__ void k_finalize(int stage) {
    int b = threadIdx.x;
    if (b < BB) {
        double s  = g_stats[stage][b][0];
        double ss = g_stats[stage][b][1];
        const double cnt = (double)HH * (double)NN;
        double mean = s / cnt;
        double var  = (ss - s * s / cnt) / (cnt - 1.0);
        if (var < 0.0) var = 0.0;
        double sd = sqrt(var) + 1e-5;
        g_norm[stage][b][0] = (float)mean;
        g_norm[stage][b][1] = (float)(1.0 / sd);
    }
}

// ---------------- MLP layer 1: h = relu([norm2relu(x2), z] @ W1 + b1) -------
// Same tiling as k_conv, identity "gather", K = 320. Writes to g_out1 (reused).
__global__ void __launch_bounds__(256) k_mlp1(const float* __restrict__ z,
                                              const float* __restrict__ w1,
                                              const float* __restrict__ b1) {
    const int b    = blockIdx.z;
    const int ht0  = blockIdx.y * 128;
    const int nt0  = blockIdx.x * 64;
    const int tid  = threadIdx.x;
    const int lane = tid & 31, warp = tid >> 5;

    __shared__ float Asm[64][33];
    __shared__ float Wsm[32][128];

    const float mean = g_norm[1][b][0];
    const float istd = g_norm[1][b][1];

    float acc[8][4];
#pragma unroll
    for (int r = 0; r < 8; r++)
#pragma unroll
        for (int q = 0; q < 4; q++) acc[r][q] = 0.f;

    const float* srcb = g_out2 + (size_t)b * NN * HH;

    for (int k0 = 0; k0 < HH + LL; k0 += 32) {
        __syncthreads();
#pragma unroll
        for (int r = 0; r < 8; r++) {
            int n  = warp * 8 + r;
            int gn = nt0 + n;
            float v;
            if (k0 < HH) {
                v = srcb[(size_t)gn * HH + k0 + lane];
                v = fmaxf((v - mean) * istd, 0.f);
            } else {
                v = z[b * LL + (k0 - HH) + lane];
            }
            Asm[n][lane] = v;
        }
#pragma unroll
        for (int i = 0; i < 16; i++) {
            int li = tid + i * 256;
            int kk = li >> 7, hh = li & 127;
            Wsm[kk][hh] = w1[(k0 + kk) * HH + ht0 + hh];
        }
        __syncthreads();
#pragma unroll
        for (int kk = 0; kk < 32; kk++) {
            float4 w4 = *(const float4*)&Wsm[kk][lane * 4];
#pragma unroll
            for (int r = 0; r < 8; r++) {
                float a = Asm[warp * 8 + r][kk];
                acc[r][0] = fmaf(a, w4.x, acc[r][0]);
                acc[r][1] = fmaf(a, w4.y, acc[r][1]);
                acc[r][2] = fmaf(a, w4.z, acc[r][2]);
                acc[r][3] = fmaf(a, w4.w, acc[r][3]);
            }
        }
    }

    float4 bv = *(const float4*)&b1[ht0 + lane * 4];
#pragma unroll
    for (int r = 0; r < 8; r++) {
        int gn = nt0 + warp * 8 + r;
        float4 o;
        o.x = fmaxf(acc[r][0] + bv.x, 0.f);
        o.y = fmaxf(acc[r][1] + bv.y, 0.f);
        o.z = fmaxf(acc[r][2] + bv.z, 0.f);
        o.w = fmaxf(acc[r][3] + bv.w, 0.f);
        *(float4*)&g_out1[((size_t)b * NN + gn) * HH + ht0 + lane * 4] = o;
    }
}

// ---------------- MLP layer 2: out = h @ W2 + b2 (K=256, P=32) --------------
__global__ void __launch_bounds__(256) k_mlp2(const float* __restrict__ w2,
                                              const float* __restrict__ b2,
                                              float* __restrict__ out) {
    __shared__ float W2s[HH * PP];     // [k][p], 32 KB
    __shared__ float Hs[32][257];      // 32 nodes x 256 k
    const int b   = blockIdx.y;
    const int n0  = blockIdx.x * 32;
    const int tid = threadIdx.x;

    for (int i = tid; i < HH * PP; i += 256) W2s[i] = w2[i];
    for (int i = tid; i < 32 * HH; i += 256) {
        int n = i >> 8, k = i & 255;
        Hs[n][k] = g_out1[((size_t)b * NN + n0 + n) * HH + k];
    }
    __syncthreads();

    const int p  = tid & 31;
    const int nq = tid >> 5;
    const float bias = b2[p];
#pragma unroll
    for (int rr = 0; rr < 4; rr++) {
        int n = nq * 4 + rr;
        float acc = bias;
#pragma unroll 8
        for (int k = 0; k < HH; k++)
            acc = fmaf(Hs[n][k], W2s[k * PP + p], acc);
        out[((size_t)b * NN + n0 + n) * PP + p] = acc;
    }
}

// ---------------- launch -----------------------------------------------------
extern "C" void kernel_launch(void* const* d_in, const int* in_sizes, int n_in,
                              void* d_out, int out_size) {
    (void)in_sizes; (void)n_in; (void)out_size;
    const float* node_feats = (const float*)d_in[0];
    const float* z          = (const float*)d_in[1];
    const int*   children   = (const int*)  d_in[2];
    const float* conv1_w    = (const float*)d_in[3];
    const float* conv1_b    = (const float*)d_in[4];
    const float* conv2_w    = (const float*)d_in[5];
    const float* conv2_b    = (const float*)d_in[6];
    const float* mlp_w1     = (const float*)d_in[7];
    const float* mlp_b1     = (const float*)d_in[8];
    const float* mlp_w2     = (const float*)d_in[9];
    const float* mlp_b2     = (const float*)d_in[10];
    float* out = (float*)d_out;

    k_init<<<64, 256>>>();
    k_transpose<<<dim3(NN / 32, CC / 32, BB), dim3(32, 32)>>>(node_feats);
    k_repack<<<256, 256>>>(conv1_w, conv2_w);

    k_conv<CC, 0><<<dim3(32, 2, BB), 256>>>(conv1_b, children);   // 32 node-tiles cover 2047
    k_finalize<<<1, 64>>>(0);
    k_conv<HH, 1><<<dim3(32, 2, BB), 256>>>(conv2_b, children);
    k_finalize<<<1, 64>>>(1);

    k_mlp1<<<dim3(NN / 64, 2, BB), 256>>>(z, mlp_w1, mlp_b1);
    k_mlp2<<<dim3(NN / 32, BB), 256>>>(mlp_w2, mlp_b2, out);
}

// round 3
// speedup vs baseline: 2.2542x; 2.2542x over previous
#include <cuda_runtime.h>
#include <cuda_bf16.h>
#include <cstdint>
#include <math.h>

#define BB   64
#define CC   64
#define HH   256
#define LL   64
#define PP   32
#define NREAL 2047
#define NN   2048
#define KTOT 1280   // 192 (conv1) + 768 (conv2) + 320 (mlp1)

// ---------------- global scratch ---------------------------------------------
__device__ float g_xt0 [(size_t)BB * NN * CC];
__device__ float g_out1[(size_t)BB * NN * HH];
__device__ float g_out2[(size_t)BB * NN * HH];
__device__ __align__(16) __nv_bfloat16 g_wpHi[HH * KTOT];  // [h][k] packed, k contiguous
__device__ __align__(16) __nv_bfloat16 g_wpLo[HH * KTOT];
__device__ double g_stats[2][BB][2];
__device__ float  g_norm [2][BB][2];

// ---------------- helpers -----------------------------------------------------
__device__ __forceinline__ uint32_t smem_u32(const void* p) {
    uint32_t a;
    asm("{ .reg .u64 t; cvta.to.shared.u64 t, %1; cvt.u32.u64 %0, t; }" : "=r"(a) : "l"(p));
    return a;
}
__device__ __forceinline__ void ldm4(uint32_t* r, uint32_t addr) {
    asm volatile("ldmatrix.sync.aligned.m8n8.x4.shared.b16 {%0,%1,%2,%3}, [%4];"
                 : "=r"(r[0]), "=r"(r[1]), "=r"(r[2]), "=r"(r[3]) : "r"(addr));
}
__device__ __forceinline__ void mma16816(float* c, const uint32_t* a, uint32_t b0, uint32_t b1) {
    asm volatile("mma.sync.aligned.m16n8k16.row.col.f32.bf16.bf16.f32 "
                 "{%0,%1,%2,%3}, {%4,%5,%6,%7}, {%8,%9}, {%0,%1,%2,%3};"
                 : "+f"(c[0]), "+f"(c[1]), "+f"(c[2]), "+f"(c[3])
                 : "r"(a[0]), "r"(a[1]), "r"(a[2]), "r"(a[3]), "r"(b0), "r"(b1));
}
__device__ __forceinline__ uint32_t pk(__nv_bfloat16 a, __nv_bfloat16 b) {
    return (uint32_t)__bfloat16_as_ushort(a) | ((uint32_t)__bfloat16_as_ushort(b) << 16);
}

// ---------------- init: zero stats + node-0 rows ------------------------------
__global__ void k_init() {
    int t = blockIdx.x * blockDim.x + threadIdx.x;
    if (t < 2 * BB * 2) ((double*)g_stats)[t] = 0.0;
    for (int i = t; i < BB * HH; i += gridDim.x * blockDim.x) {
        int b = i >> 8, h = i & 255;
        g_out1[(size_t)b * NN * HH + h] = 0.f;
        g_out2[(size_t)b * NN * HH + h] = 0.f;
    }
}

// ---------------- transpose node_feats [B,C,N] -> [B,N,C] ----------------------
__global__ void k_transpose(const float* __restrict__ x) {
    __shared__ float tile[32][33];
    int b  = blockIdx.z;
    int n0 = blockIdx.x * 32;
    int c0 = blockIdx.y * 32;
    int tx = threadIdx.x, ty = threadIdx.y;
    tile[ty][tx] = x[((size_t)b * CC + c0 + ty) * NN + n0 + tx];
    __syncthreads();
    g_xt0[((size_t)b * NN + n0 + ty) * CC + c0 + tx] = tile[tx][ty];
}

// ---------------- pack weights into [h][k] hi/lo bf16 --------------------------
// k layout: [0,192) conv1 (j=k/64,c=k%64); [192,960) conv2 (j=kk/256,c=kk%256);
//           [960,1280) mlp1 row kk = k-960 of w1[320][256].
__global__ void k_pack(const float* __restrict__ w1c, const float* __restrict__ w2c,
                       const float* __restrict__ wm) {
    int t = blockIdx.x * blockDim.x + threadIdx.x;
    for (int e = t; e < HH * KTOT; e += gridDim.x * blockDim.x) {
        int h = e / KTOT, k = e % KTOT;
        float w;
        if (k < 192)      { int j = k / 64,  c = k % 64;           w = w1c[(h * CC + c) * 3 + j]; }
        else if (k < 960) { int kk = k - 192; int j = kk / 256, c = kk % 256; w = w2c[(h * HH + c) * 3 + j]; }
        else              { int kk = k - 960; w = wm[kk * HH + h]; }
        __nv_bfloat16 hi = __float2bfloat16(w);
        __nv_bfloat16 lo = __float2bfloat16(w - __bfloat162float(hi));
        g_wpHi[e] = hi;
        g_wpLo[e] = lo;
    }
}

// ---------------- fused gather + mma.sync GEMM ---------------------------------
// STAGE 0: conv1  src=g_xt0  (CIN=64,  K=192, gather)              -> g_out1 + stats0
// STAGE 1: conv2  src=g_out1 (CIN=256, K=768, gather, norm0+relu)  -> g_out2 + stats1
// STAGE 2: mlp1   src=g_out2 (K=320 = 256 feat norm1+relu + 64 z)  -> relu -> g_out1
// CTA: 256 thr = 8 warps (4 M x 2 N). CTA tile 128 nodes x 128 h. K-chunk 32.
template <int STAGE>
__global__ void __launch_bounds__(256, 2) k_gemm(const float* __restrict__ bias,
                                                 const int* __restrict__ children,
                                                 const float* __restrict__ zin) {
    constexpr int CIN   = (STAGE == 0) ? 64 : 256;
    constexpr int NCH   = (STAGE == 0) ? 6 : (STAGE == 1) ? 24 : 10;
    constexpr int KBASE = (STAGE == 0) ? 0 : (STAGE == 1) ? 192 : 960;

    __shared__ __align__(16) __nv_bfloat16 Asm[2][128][40];
    __shared__ __align__(16) __nv_bfloat16 Bsm[2][128][40];
    __shared__ int   sidx[384];
    __shared__ float rs[8], rss[8];

    const int tile = blockIdx.x, hb = blockIdx.y, b = blockIdx.z;
    const int h0   = hb * 128;
    const int nbase = (STAGE == 2) ? tile * 128 : 1 + tile * 128;
    const int tid = threadIdx.x, lane = tid & 31, wid = tid >> 5;
    const int wm = wid & 3, wn = wid >> 2;

    float mean = 0.f, istd = 1.f;
    if (STAGE >= 1) { mean = g_norm[STAGE - 1][b][0]; istd = g_norm[STAGE - 1][b][1]; }

    if (STAGE < 2) {
        for (int i = tid; i < 384; i += 256) {
            int gn = nbase + i / 3;
            sidx[i] = (gn <= NREAL) ? children[b * 3 * NREAL + (gn - 1) * 3 + (i % 3)] : 0;
        }
    }

    const float* srcb = ((STAGE == 0) ? g_xt0 : (STAGE == 1) ? g_out1 : g_out2)
                        + (size_t)b * NN * CIN;

    float acc[2][8][4];
#pragma unroll
    for (int mt = 0; mt < 2; mt++)
#pragma unroll
        for (int nt = 0; nt < 8; nt++)
#pragma unroll
            for (int q = 0; q < 4; q++) acc[mt][nt][q] = 0.f;

    const int m = tid >> 1, half = tid & 1;   // A/B producer row & half

    const uint32_t aB0 = smem_u32(&Asm[0][0][0]);
    const uint32_t aB1 = smem_u32(&Asm[1][0][0]);
    const uint32_t bB0 = smem_u32(&Bsm[0][0][0]);
    const uint32_t bB1 = smem_u32(&Bsm[1][0][0]);

    __syncthreads();   // sidx visible

    for (int qc = 0; qc < NCH; ++qc) {
        int j = 0, c0 = 0;
        if (STAGE == 0)      { j = qc >> 1; c0 = (qc & 1) * 32; }
        else if (STAGE == 1) { j = qc >> 3; c0 = (qc & 7) * 32; }
        else                 { c0 = qc * 32; }

        // -------- global loads into registers --------
        float4 av[4];
        if (STAGE == 2 && c0 >= 256) {
            const float4* zp = (const float4*)(zin + b * LL + (c0 - 256) + half * 16);
#pragma unroll
            for (int f = 0; f < 4; f++) av[f] = zp[f];
        } else {
            int row = (STAGE == 2) ? (nbase + m) : sidx[m * 3 + j];
            const float4* p = (const float4*)(srcb + (size_t)row * CIN + c0 + half * 16);
#pragma unroll
            for (int f = 0; f < 4; f++) av[f] = p[f];
            if (STAGE >= 1) {
#pragma unroll
                for (int f = 0; f < 4; f++) {
                    av[f].x = fmaxf((av[f].x - mean) * istd, 0.f);
                    av[f].y = fmaxf((av[f].y - mean) * istd, 0.f);
                    av[f].z = fmaxf((av[f].z - mean) * istd, 0.f);
                    av[f].w = fmaxf((av[f].w - mean) * istd, 0.f);
                }
            }
        }
        const size_t boff = (size_t)(h0 + m) * KTOT + KBASE + qc * 32 + half * 16;
        uint4 bh0 = *(const uint4*)(g_wpHi + boff);
        uint4 bh1 = *(const uint4*)(g_wpHi + boff + 8);
        uint4 bl0 = *(const uint4*)(g_wpLo + boff);
        uint4 bl1 = *(const uint4*)(g_wpLo + boff + 8);

        __syncthreads();   // previous chunk's mma done reading smem

        // -------- convert + store A, store B --------
        uint32_t hi[8], lo[8];
#pragma unroll
        for (int f = 0; f < 4; f++) {
            __nv_bfloat16 h0b = __float2bfloat16(av[f].x), h1b = __float2bfloat16(av[f].y),
                          h2b = __float2bfloat16(av[f].z), h3b = __float2bfloat16(av[f].w);
            __nv_bfloat16 l0b = __float2bfloat16(av[f].x - __bfloat162float(h0b)),
                          l1b = __float2bfloat16(av[f].y - __bfloat162float(h1b)),
                          l2b = __float2bfloat16(av[f].z - __bfloat162float(h2b)),
                          l3b = __float2bfloat16(av[f].w - __bfloat162float(h3b));
            hi[2 * f] = pk(h0b, h1b); hi[2 * f + 1] = pk(h2b, h3b);
            lo[2 * f] = pk(l0b, l1b); lo[2 * f + 1] = pk(l2b, l3b);
        }
        *(uint4*)&Asm[0][m][half * 16]     = make_uint4(hi[0], hi[1], hi[2], hi[3]);
        *(uint4*)&Asm[0][m][half * 16 + 8] = make_uint4(hi[4], hi[5], hi[6], hi[7]);
        *(uint4*)&Asm[1][m][half * 16]     = make_uint4(lo[0], lo[1], lo[2], lo[3]);
        *(uint4*)&Asm[1][m][half * 16 + 8] = make_uint4(lo[4], lo[5], lo[6], lo[7]);
        *(uint4*)&Bsm[0][m][half * 16]     = bh0;
        *(uint4*)&Bsm[0][m][half * 16 + 8] = bh1;
        *(uint4*)&Bsm[1][m][half * 16]     = bl0;
        *(uint4*)&Bsm[1][m][half * 16 + 8] = bl1;

        __syncthreads();

        // -------- mma over 2 x k16 steps --------
#pragma unroll
        for (int s = 0; s < 2; s++) {
            const uint32_t colB = (uint32_t)(s * 16 + (lane >> 4) * 8) * 2u;
            const uint32_t arow = (uint32_t)(wm * 32 + (lane & 15)) * 80u;
            uint32_t afh[2][4], afl[2][4];
            ldm4(afh[0], aB0 + arow + colB);
            ldm4(afh[1], aB0 + arow + 16 * 80 + colB);
            ldm4(afl[0], aB1 + arow + colB);
            ldm4(afl[1], aB1 + arow + 16 * 80 + colB);
            const uint32_t brow = (uint32_t)(wn * 64 + (lane & 15)) * 80u;
#pragma unroll
            for (int jp = 0; jp < 4; jp++) {
                uint32_t r[4];
                ldm4(r, bB0 + brow + (uint32_t)jp * 16 * 80 + colB);
#pragma unroll
                for (int mt = 0; mt < 2; mt++) {
                    mma16816(acc[mt][2 * jp],     afh[mt], r[0], r[2]);
                    mma16816(acc[mt][2 * jp],     afl[mt], r[0], r[2]);
                    mma16816(acc[mt][2 * jp + 1], afh[mt], r[1], r[3]);
                    mma16816(acc[mt][2 * jp + 1], afl[mt], r[1], r[3]);
                }
            }
#pragma unroll
            for (int jp = 0; jp < 4; jp++) {
                uint32_t r[4];
                ldm4(r, bB1 + brow + (uint32_t)jp * 16 * 80 + colB);
#pragma unroll
                for (int mt = 0; mt < 2; mt++) {
                    mma16816(acc[mt][2 * jp],     afh[mt], r[0], r[2]);
                    mma16816(acc[mt][2 * jp + 1], afh[mt], r[1], r[3]);
                }
            }
        }
    }

    // -------- epilogue: bias (+relu), store fp32, stats --------
    float* dst = (STAGE == 1) ? g_out2 : g_out1;
    float s = 0.f, ss = 0.f;
#pragma unroll
    for (int mt = 0; mt < 2; mt++) {
#pragma unroll
        for (int hr = 0; hr < 2; hr++) {
            int rrow = wm * 32 + mt * 16 + (lane >> 2) + hr * 8;
            int gn   = nbase + rrow;
            bool valid = (STAGE == 2) || (gn <= NREAL);
            if (valid) {
                float* drow = dst + ((size_t)b * NN + gn) * HH;
#pragma unroll
                for (int nt = 0; nt < 8; nt++) {
                    int col = h0 + wn * 64 + nt * 8 + (lane & 3) * 2;
                    float o0 = acc[mt][nt][hr * 2 + 0] + bias[col];
                    float o1 = acc[mt][nt][hr * 2 + 1] + bias[col + 1];
                    if (STAGE == 2) { o0 = fmaxf(o0, 0.f); o1 = fmaxf(o1, 0.f); }
                    *(float2*)&drow[col] = make_float2(o0, o1);
                    if (STAGE != 2) { s += o0 + o1; ss += o0 * o0 + o1 * o1; }
                }
            }
        }
    }
    if (STAGE != 2) {
#pragma unroll
        for (int off = 16; off > 0; off >>= 1) {
            s  += __shfl_down_sync(0xffffffffu, s,  off);
            ss += __shfl_down_sync(0xffffffffu, ss, off);
        }
        if (lane == 0) { rs[wid] = s; rss[wid] = ss; }
        __syncthreads();
        if (tid == 0) {
            float S = 0.f, SS = 0.f;
#pragma unroll
            for (int w = 0; w < 8; w++) { S += rs[w]; SS += rss[w]; }
            atomicAdd(&g_stats[STAGE][b][0], (double)S);
            atomicAdd(&g_stats[STAGE][b][1], (double)SS);
        }
    }
}

// ---------------- finalize norm stats ------------------------------------------
__global__ void k_finalize(int stage) {
    int b = threadIdx.x;
    if (b < BB) {
        double s  = g_stats[stage][b][0];
        double ss = g_stats[stage][b][1];
        const double cnt = (double)HH * (double)NN;
        double mean = s / cnt;
        double var  = (ss - s * s / cnt) / (cnt - 1.0);
        if (var < 0.0) var = 0.0;
        double sd = sqrt(var) + 1e-5;
        g_norm[stage][b][0] = (float)mean;
        g_norm[stage][b][1] = (float)(1.0 / sd);
    }
}

// ---------------- MLP layer 2: out = h @ W2 + b2 (K=256, P=32) ------------------
__global__ void __launch_bounds__(256) k_mlp2(const float* __restrict__ w2,
                                              const float* __restrict__ b2,
                                              float* __restrict__ out) {
    __shared__ float W2s[HH * PP];
    __shared__ float Hs[32][257];
    const int b   = blockIdx.y;
    const int n0  = blockIdx.x * 32;
    const int tid = threadIdx.x;

    for (int i = tid; i < HH * PP; i += 256) W2s[i] = w2[i];
    for (int i = tid; i < 32 * HH; i += 256) {
        int n = i >> 8, k = i & 255;
        Hs[n][k] = g_out1[((size_t)b * NN + n0 + n) * HH + k];
    }
    __syncthreads();

    const int p  = tid & 31;
    const int nq = tid >> 5;
    const float bias = b2[p];
#pragma unroll
    for (int rr = 0; rr < 4; rr++) {
        int n = nq * 4 + rr;
        float acc = bias;
#pragma unroll 8
        for (int k = 0; k < HH; k++)
            acc = fmaf(Hs[n][k], W2s[k * PP + p], acc);
        out[((size_t)b * NN + n0 + n) * PP + p] = acc;
    }
}

// ---------------- launch ---------------------------------------------------------
extern "C" void kernel_launch(void* const* d_in, const int* in_sizes, int n_in,
                              void* d_out, int out_size) {
    (void)in_sizes; (void)n_in; (void)out_size;
    const float* node_feats = (const float*)d_in[0];
    const float* z          = (const float*)d_in[1];
    const int*   children   = (const int*)  d_in[2];
    const float* conv1_w    = (const float*)d_in[3];
    const float* conv1_b    = (const float*)d_in[4];
    const float* conv2_w    = (const float*)d_in[5];
    const float* conv2_b    = (const float*)d_in[6];
    const float* mlp_w1     = (const float*)d_in[7];
    const float* mlp_b1     = (const float*)d_in[8];
    const float* mlp_w2     = (const float*)d_in[9];
    const float* mlp_b2     = (const float*)d_in[10];
    float* out = (float*)d_out;

    k_init<<<64, 256>>>();
    k_transpose<<<dim3(NN / 32, CC / 32, BB), dim3(32, 32)>>>(node_feats);
    k_pack<<<256, 256>>>(conv1_w, conv2_w, mlp_w1);

    k_gemm<0><<<dim3(16, 2, BB), 256>>>(conv1_b, children, z);
    k_finalize<<<1, 64>>>(0);
    k_gemm<1><<<dim3(16, 2, BB), 256>>>(conv2_b, children, z);
    k_finalize<<<1, 64>>>(1);
    k_gemm<2><<<dim3(16, 2, BB), 256>>>(mlp_b1, children, z);

    k_mlp2<<<dim3(NN / 32, BB), 256>>>(mlp_w2, mlp_b2, out);
}

// round 4
// speedup vs baseline: 2.7668x; 1.2274x over previous
#include <cuda_runtime.h>
#include <cuda_bf16.h>
#include <cstdint>
#include <math.h>

#define BB   64
#define CC   64
#define HH   256
#define LL   64
#define PP   32
#define NREAL 2047
#define NN   2048
#define KTOT 1280   // 192 (conv1) + 768 (conv2) + 320 (mlp1)

// ---------------- global scratch ---------------------------------------------
__device__ float g_xt0 [(size_t)BB * NN * CC];
__device__ float g_out1[(size_t)BB * NN * HH];
__device__ float g_out2[(size_t)BB * NN * HH];
__device__ __align__(16) __nv_bfloat16 g_wpHi[HH * KTOT];  // [h][k], k contiguous
__device__ __align__(16) __nv_bfloat16 g_wpLo[HH * KTOT];
__device__ __align__(16) __nv_bfloat16 g_w2Hi[PP * HH];    // [p][k]
__device__ __align__(16) __nv_bfloat16 g_w2Lo[PP * HH];
__device__ double g_stats[2][BB][2];
__device__ float  g_norm [2][BB][2];

// ---------------- smem layouts (dynamic) ---------------------------------------
// k_gemm: A stages: (st*2+pl)*10240 ; B at 40960 + (st*2+pl)*10240
#define GA_OFF   0
#define GB_OFF   40960
#define GSIDX    81920
#define GRS      83456
#define GRSS     83488
#define GEMM_SMEM 83520
// k_mlp2: A stages 4*10240 at 0; W2 planes at 40960 (pitch 264 elems = 528B)
#define M2A_OFF  0
#define M2W_OFF  40960
#define M2_SMEM  74752

// ---------------- helpers -------------------------------------------------------
__device__ __forceinline__ uint32_t smem_u32(const void* p) {
    uint32_t a;
    asm("{ .reg .u64 t; cvta.to.shared.u64 t, %1; cvt.u32.u64 %0, t; }" : "=r"(a) : "l"(p));
    return a;
}
__device__ __forceinline__ void ldm4(uint32_t* r, uint32_t addr) {
    asm volatile("ldmatrix.sync.aligned.m8n8.x4.shared.b16 {%0,%1,%2,%3}, [%4];"
                 : "=r"(r[0]), "=r"(r[1]), "=r"(r[2]), "=r"(r[3]) : "r"(addr));
}
__device__ __forceinline__ void mma16816(float* c, const uint32_t* a, uint32_t b0, uint32_t b1) {
    asm volatile("mma.sync.aligned.m16n8k16.row.col.f32.bf16.bf16.f32 "
                 "{%0,%1,%2,%3}, {%4,%5,%6,%7}, {%8,%9}, {%0,%1,%2,%3};"
                 : "+f"(c[0]), "+f"(c[1]), "+f"(c[2]), "+f"(c[3])
                 : "r"(a[0]), "r"(a[1]), "r"(a[2]), "r"(a[3]), "r"(b0), "r"(b1));
}
__device__ __forceinline__ void cp16(uint32_t dst, const void* src) {
    asm volatile("cp.async.ca.shared.global [%0], [%1], 16;" :: "r"(dst), "l"(src));
}
#define CP_COMMIT() asm volatile("cp.async.commit_group;" ::: "memory")
#define CP_WAIT0()  asm volatile("cp.async.wait_group 0;"  ::: "memory")
__device__ __forceinline__ uint32_t pk(__nv_bfloat16 a, __nv_bfloat16 b) {
    return (uint32_t)__bfloat16_as_ushort(a) | ((uint32_t)__bfloat16_as_ushort(b) << 16);
}

// ---------------- init -----------------------------------------------------------
__global__ void k_init() {
    int t = blockIdx.x * blockDim.x + threadIdx.x;
    if (t < 2 * BB * 2) ((double*)g_stats)[t] = 0.0;
    for (int i = t; i < BB * HH; i += gridDim.x * blockDim.x) {
        int b = i >> 8, h = i & 255;
        g_out1[(size_t)b * NN * HH + h] = 0.f;
        g_out2[(size_t)b * NN * HH + h] = 0.f;
    }
}

// ---------------- transpose node_feats [B,C,N] -> [B,N,C] --------------------------
__global__ void k_transpose(const float* __restrict__ x) {
    __shared__ float tile[32][33];
    int b  = blockIdx.z;
    int n0 = blockIdx.x * 32;
    int c0 = blockIdx.y * 32;
    int tx = threadIdx.x, ty = threadIdx.y;
    tile[ty][tx] = x[((size_t)b * CC + c0 + ty) * NN + n0 + tx];
    __syncthreads();
    g_xt0[((size_t)b * NN + n0 + ty) * CC + c0 + tx] = tile[tx][ty];
}

// ---------------- pack weights into bf16 hi/lo -------------------------------------
__global__ void k_pack(const float* __restrict__ w1c, const float* __restrict__ w2c,
                       const float* __restrict__ wm, const float* __restrict__ wm2) {
    int t = blockIdx.x * blockDim.x + threadIdx.x;
    int stride = gridDim.x * blockDim.x;
    for (int e = t; e < HH * KTOT; e += stride) {
        int h = e / KTOT, k = e % KTOT;
        float w;
        if (k < 192)      { int j = k / 64,  c = k % 64;            w = w1c[(h * CC + c) * 3 + j]; }
        else if (k < 960) { int kk = k - 192; int j = kk / 256, c = kk % 256; w = w2c[(h * HH + c) * 3 + j]; }
        else              { int kk = k - 960; w = wm[kk * HH + h]; }
        __nv_bfloat16 hi = __float2bfloat16(w);
        g_wpHi[e] = hi;
        g_wpLo[e] = __float2bfloat16(w - __bfloat162float(hi));
    }
    for (int e = t; e < PP * HH; e += stride) {
        int p = e >> 8, k = e & 255;
        float w = wm2[k * PP + p];
        __nv_bfloat16 hi = __float2bfloat16(w);
        g_w2Hi[e] = hi;
        g_w2Lo[e] = __float2bfloat16(w - __bfloat162float(hi));
    }
}

// ---------------- fused gather + mma.sync GEMM (pipelined) --------------------------
// STAGE 0: conv1 src=g_xt0 (CIN=64, K=192, gather)             -> g_out1 + stats0
// STAGE 1: conv2 src=g_out1 (CIN=256, K=768, gather,norm+relu) -> g_out2 + stats1
// STAGE 2: mlp1  src=g_out2 (K=320: 256 norm+relu, 64 z)       -> relu -> g_out1
template <int STAGE>
__global__ void __launch_bounds__(256, 2) k_gemm(const float* __restrict__ bias,
                                                 const int* __restrict__ children,
                                                 const float* __restrict__ zin) {
    extern __shared__ __align__(16) char smem[];
    constexpr int CIN   = (STAGE == 0) ? 64 : 256;
    constexpr int NCH   = (STAGE == 0) ? 6 : (STAGE == 1) ? 24 : 10;
    constexpr int KBASE = (STAGE == 0) ? 0 : (STAGE == 1) ? 192 : 960;

    const int tile = blockIdx.x, hb = blockIdx.y, b = blockIdx.z;
    const int h0   = hb * 128;
    const int nbase = (STAGE == 2) ? tile * 128 : 1 + tile * 128;
    const int tid = threadIdx.x, lane = tid & 31, wid = tid >> 5;
    const int wm = wid & 3, wn = wid >> 2;
    const uint32_t sb = smem_u32(smem);
    int* sidx = (int*)(smem + GSIDX);

    float mean = 0.f, istd = 1.f;
    if (STAGE >= 1) { mean = g_norm[STAGE - 1][b][0]; istd = g_norm[STAGE - 1][b][1]; }

    if (STAGE < 2) {
        for (int i = tid; i < 384; i += 256) {
            int gn = nbase + i / 3;
            sidx[i] = (gn <= NREAL) ? children[b * 3 * NREAL + (gn - 1) * 3 + (i % 3)] : 0;
        }
        __syncthreads();
    }

    const float* srcb = ((STAGE == 0) ? g_xt0 : (STAGE == 1) ? g_out1 : g_out2)
                        + (size_t)b * NN * CIN;
    const int m = tid >> 1, half = tid & 1;

    float acc[2][8][4];
#pragma unroll
    for (int mt = 0; mt < 2; mt++)
#pragma unroll
        for (int nt = 0; nt < 8; nt++)
#pragma unroll
            for (int q = 0; q < 4; q++) acc[mt][nt][q] = 0.f;

    // ---- helpers ----
    auto copyB = [&](int qc, int st) {
        const int kofs = KBASE + qc * 32;
#pragma unroll
        for (int pl = 0; pl < 2; ++pl) {
            const __nv_bfloat16* gw = (pl ? g_wpLo : g_wpHi);
            uint32_t dbase = sb + GB_OFF + (uint32_t)(st * 2 + pl) * 10240u;
#pragma unroll
            for (int u = 0; u < 2; ++u) {
                int seg = tid + u * 256;
                int row = seg >> 2, s4 = seg & 3;
                cp16(dbase + (uint32_t)row * 80u + (uint32_t)s4 * 16u,
                     gw + (size_t)(h0 + row) * KTOT + kofs + s4 * 8);
            }
        }
    };
    auto loadA = [&](int qc, float4* av) {
        int j = 0, c0 = 0;
        if (STAGE == 0)      { j = qc >> 1; c0 = (qc & 1) * 32; }
        else if (STAGE == 1) { j = qc >> 3; c0 = (qc & 7) * 32; }
        else                 { c0 = qc * 32; }
        if (STAGE == 2 && c0 >= 256) {
            const float4* zp = (const float4*)(zin + b * LL + (c0 - 256) + half * 16);
#pragma unroll
            for (int f = 0; f < 4; f++) av[f] = zp[f];
        } else {
            int row = (STAGE == 2) ? (nbase + m) : sidx[m * 3 + j];
            const float4* p = (const float4*)(srcb + (size_t)row * CIN + c0 + half * 16);
#pragma unroll
            for (int f = 0; f < 4; f++) av[f] = p[f];
            if (STAGE >= 1) {
#pragma unroll
                for (int f = 0; f < 4; f++) {
                    av[f].x = fmaxf((av[f].x - mean) * istd, 0.f);
                    av[f].y = fmaxf((av[f].y - mean) * istd, 0.f);
                    av[f].z = fmaxf((av[f].z - mean) * istd, 0.f);
                    av[f].w = fmaxf((av[f].w - mean) * istd, 0.f);
                }
            }
        }
    };
    auto cvtStsA = [&](const float4* av, int st) {
        uint32_t hi[8], lo[8];
#pragma unroll
        for (int f = 0; f < 4; f++) {
            __nv_bfloat16 h0b = __float2bfloat16(av[f].x), h1b = __float2bfloat16(av[f].y),
                          h2b = __float2bfloat16(av[f].z), h3b = __float2bfloat16(av[f].w);
            __nv_bfloat16 l0b = __float2bfloat16(av[f].x - __bfloat162float(h0b)),
                          l1b = __float2bfloat16(av[f].y - __bfloat162float(h1b)),
                          l2b = __float2bfloat16(av[f].z - __bfloat162float(h2b)),
                          l3b = __float2bfloat16(av[f].w - __bfloat162float(h3b));
            hi[2 * f] = pk(h0b, h1b); hi[2 * f + 1] = pk(h2b, h3b);
            lo[2 * f] = pk(l0b, l1b); lo[2 * f + 1] = pk(l2b, l3b);
        }
        char* aH = smem + GA_OFF + (st * 2 + 0) * 10240 + m * 80 + half * 32;
        char* aL = smem + GA_OFF + (st * 2 + 1) * 10240 + m * 80 + half * 32;
        *(uint4*)(aH)      = make_uint4(hi[0], hi[1], hi[2], hi[3]);
        *(uint4*)(aH + 16) = make_uint4(hi[4], hi[5], hi[6], hi[7]);
        *(uint4*)(aL)      = make_uint4(lo[0], lo[1], lo[2], lo[3]);
        *(uint4*)(aL + 16) = make_uint4(lo[4], lo[5], lo[6], lo[7]);
    };

    // ---- prologue ----
    float4 av[4];
    copyB(0, 0); CP_COMMIT();
    loadA(0, av);
    cvtStsA(av, 0);
    CP_WAIT0();
    __syncthreads();

    // ---- main loop: one sync per chunk ----
    for (int qc = 0; qc < NCH; ++qc) {
        const int cst = qc & 1, nst = cst ^ 1;
        const bool more = (qc + 1 < NCH);
        if (more) {
            copyB(qc + 1, nst); CP_COMMIT();
            loadA(qc + 1, av);
        }
        const uint32_t aB0 = sb + GA_OFF + (uint32_t)(cst * 2) * 10240u;
        const uint32_t aB1 = aB0 + 10240u;
        const uint32_t bB0 = sb + GB_OFF + (uint32_t)(cst * 2) * 10240u;
        const uint32_t bB1 = bB0 + 10240u;
#pragma unroll
        for (int s = 0; s < 2; s++) {
            const uint32_t colB = (uint32_t)(s * 16 + (lane >> 4) * 8) * 2u;
            const uint32_t arow = (uint32_t)(wm * 32 + (lane & 15)) * 80u;
            uint32_t afh[2][4], afl[2][4];
            ldm4(afh[0], aB0 + arow + colB);
            ldm4(afh[1], aB0 + arow + 16 * 80 + colB);
            ldm4(afl[0], aB1 + arow + colB);
            ldm4(afl[1], aB1 + arow + 16 * 80 + colB);
            const uint32_t brow = (uint32_t)(wn * 64 + (lane & 15)) * 80u;
#pragma unroll
            for (int jp = 0; jp < 4; jp++) {
                uint32_t r[4];
                ldm4(r, bB0 + brow + (uint32_t)jp * 16 * 80 + colB);
#pragma unroll
                for (int mt = 0; mt < 2; mt++) {
                    mma16816(acc[mt][2 * jp],     afh[mt], r[0], r[2]);
                    mma16816(acc[mt][2 * jp],     afl[mt], r[0], r[2]);
                    mma16816(acc[mt][2 * jp + 1], afh[mt], r[1], r[3]);
                    mma16816(acc[mt][2 * jp + 1], afl[mt], r[1], r[3]);
                }
            }
#pragma unroll
            for (int jp = 0; jp < 4; jp++) {
                uint32_t r[4];
                ldm4(r, bB1 + brow + (uint32_t)jp * 16 * 80 + colB);
#pragma unroll
                for (int mt = 0; mt < 2; mt++) {
                    mma16816(acc[mt][2 * jp],     afh[mt], r[0], r[2]);
                    mma16816(acc[mt][2 * jp + 1], afh[mt], r[1], r[3]);
                }
            }
        }
        if (more) cvtStsA(av, nst);
        CP_WAIT0();
        __syncthreads();
    }

    // ---- epilogue: bias (+relu), store fp32, stats ----
    float* dst = (STAGE == 1) ? g_out2 : g_out1;
    float s = 0.f, ss = 0.f;
#pragma unroll
    for (int mt = 0; mt < 2; mt++) {
#pragma unroll
        for (int hr = 0; hr < 2; hr++) {
            int rrow = wm * 32 + mt * 16 + (lane >> 2) + hr * 8;
            int gn   = nbase + rrow;
            bool valid = (STAGE == 2) || (gn <= NREAL);
            if (valid) {
                float* drow = dst + ((size_t)b * NN + gn) * HH;
#pragma unroll
                for (int nt = 0; nt < 8; nt++) {
                    int col = h0 + wn * 64 + nt * 8 + (lane & 3) * 2;
                    float o0 = acc[mt][nt][hr * 2 + 0] + bias[col];
                    float o1 = acc[mt][nt][hr * 2 + 1] + bias[col + 1];
                    if (STAGE == 2) { o0 = fmaxf(o0, 0.f); o1 = fmaxf(o1, 0.f); }
                    *(float2*)&drow[col] = make_float2(o0, o1);
                    if (STAGE != 2) { s += o0 + o1; ss += o0 * o0 + o1 * o1; }
                }
            }
        }
    }
    if (STAGE != 2) {
#pragma unroll
        for (int off = 16; off > 0; off >>= 1) {
            s  += __shfl_down_sync(0xffffffffu, s,  off);
            ss += __shfl_down_sync(0xffffffffu, ss, off);
        }
        float* rs  = (float*)(smem + GRS);
        float* rss = (float*)(smem + GRSS);
        if (lane == 0) { rs[wid] = s; rss[wid] = ss; }
        __syncthreads();
        if (tid == 0) {
            float S = 0.f, SS = 0.f;
#pragma unroll
            for (int w = 0; w < 8; w++) { S += rs[w]; SS += rss[w]; }
            atomicAdd(&g_stats[STAGE][b][0], (double)S);
            atomicAdd(&g_stats[STAGE][b][1], (double)SS);
        }
    }
}

// ---------------- finalize norm stats ------------------------------------------
__global__ void k_finalize(int stage) {
    int b = threadIdx.x;
    if (b < BB) {
        double s  = g_stats[stage][b][0];
        double ss = g_stats[stage][b][1];
        const double cnt = (double)HH * (double)NN;
        double mean = s / cnt;
        double var  = (ss - s * s / cnt) / (cnt - 1.0);
        if (var < 0.0) var = 0.0;
        double sd = sqrt(var) + 1e-5;
        g_norm[stage][b][0] = (float)mean;
        g_norm[stage][b][1] = (float)(1.0 / sd);
    }
}

// ---------------- MLP layer 2 via mma: out = h @ W2 + b2 (K=256, P=32) ----------
// CTA: 128 nodes x 32 P. 8 warps: warp w -> rows w*16..w*16+15. W2 resident hi/lo.
__global__ void __launch_bounds__(256, 2) k_mlp2(const float* __restrict__ b2,
                                                 float* __restrict__ out) {
    extern __shared__ __align__(16) char smem[];
    const int b   = blockIdx.y;
    const int n0  = blockIdx.x * 128;
    const int tid = threadIdx.x, lane = tid & 31, wid = tid >> 5;
    const uint32_t sb = smem_u32(smem);
    const int m = tid >> 1, half = tid & 1;

    // load W2 planes once: [32 rows p][256 k], pitch 264 elems (528 B)
#pragma unroll
    for (int pl = 0; pl < 2; ++pl) {
        const __nv_bfloat16* gw = (pl ? g_w2Lo : g_w2Hi);
        char* dbase = smem + M2W_OFF + pl * 16896;
#pragma unroll
        for (int u = 0; u < 4; ++u) {
            int seg = tid + u * 256;
            int row = seg >> 5, s16 = seg & 31;
            *(uint4*)(dbase + row * 528 + s16 * 16) = *(const uint4*)(gw + row * 256 + s16 * 8);
        }
    }

    const float* srcb = g_out1 + ((size_t)b * NN + n0) * HH;

    float acc[4][4];
#pragma unroll
    for (int nt = 0; nt < 4; nt++)
#pragma unroll
        for (int q = 0; q < 4; q++) acc[nt][q] = 0.f;

    auto loadA = [&](int qc, float4* av) {
        const float4* p = (const float4*)(srcb + (size_t)m * HH + qc * 32 + half * 16);
#pragma unroll
        for (int f = 0; f < 4; f++) av[f] = p[f];
    };
    auto cvtStsA = [&](const float4* av, int st) {
        uint32_t hi[8], lo[8];
#pragma unroll
        for (int f = 0; f < 4; f++) {
            __nv_bfloat16 h0b = __float2bfloat16(av[f].x), h1b = __float2bfloat16(av[f].y),
                          h2b = __float2bfloat16(av[f].z), h3b = __float2bfloat16(av[f].w);
            __nv_bfloat16 l0b = __float2bfloat16(av[f].x - __bfloat162float(h0b)),
                          l1b = __float2bfloat16(av[f].y - __bfloat162float(h1b)),
                          l2b = __float2bfloat16(av[f].z - __bfloat162float(h2b)),
                          l3b = __float2bfloat16(av[f].w - __bfloat162float(h3b));
            hi[2 * f] = pk(h0b, h1b); hi[2 * f + 1] = pk(h2b, h3b);
            lo[2 * f] = pk(l0b, l1b); lo[2 * f + 1] = pk(l2b, l3b);
        }
        char* aH = smem + M2A_OFF + (st * 2 + 0) * 10240 + m * 80 + half * 32;
        char* aL = smem + M2A_OFF + (st * 2 + 1) * 10240 + m * 80 + half * 32;
        *(uint4*)(aH)      = make_uint4(hi[0], hi[1], hi[2], hi[3]);
        *(uint4*)(aH + 16) = make_uint4(hi[4], hi[5], hi[6], hi[7]);
        *(uint4*)(aL)      = make_uint4(lo[0], lo[1], lo[2], lo[3]);
        *(uint4*)(aL + 16) = make_uint4(lo[4], lo[5], lo[6], lo[7]);
    };

    float4 av[4];
    loadA(0, av);
    cvtStsA(av, 0);
    __syncthreads();

    const uint32_t w2H = sb + M2W_OFF;
    const uint32_t w2L = w2H + 16896u;

    for (int qc = 0; qc < 8; ++qc) {
        const int cst = qc & 1, nst = cst ^ 1;
        const bool more = (qc + 1 < 8);
        if (more) loadA(qc + 1, av);
        const uint32_t aB0 = sb + M2A_OFF + (uint32_t)(cst * 2) * 10240u;
        const uint32_t aB1 = aB0 + 10240u;
#pragma unroll
        for (int s = 0; s < 2; s++) {
            const uint32_t colB = (uint32_t)(s * 16 + (lane >> 4) * 8) * 2u;
            const uint32_t arow = (uint32_t)(wid * 16 + (lane & 15)) * 80u;
            uint32_t afh[4], afl[4];
            ldm4(afh, aB0 + arow + colB);
            ldm4(afl, aB1 + arow + colB);
            const uint32_t kbyte = (uint32_t)(qc * 32) * 2u + colB;
#pragma unroll
            for (int ng = 0; ng < 2; ng++) {
                const uint32_t brow = (uint32_t)(ng * 16 + (lane & 15)) * 528u;
                uint32_t rh[4], rl[4];
                ldm4(rh, w2H + brow + kbyte);
                ldm4(rl, w2L + brow + kbyte);
                mma16816(acc[ng * 2],     afh, rh[0], rh[2]);
                mma16816(acc[ng * 2],     afl, rh[0], rh[2]);
                mma16816(acc[ng * 2],     afh, rl[0], rl[2]);
                mma16816(acc[ng * 2 + 1], afh, rh[1], rh[3]);
                mma16816(acc[ng * 2 + 1], afl, rh[1], rh[3]);
                mma16816(acc[ng * 2 + 1], afh, rl[1], rl[3]);
            }
        }
        if (more) cvtStsA(av, nst);
        __syncthreads();
    }

    // epilogue
#pragma unroll
    for (int hr = 0; hr < 2; hr++) {
        int row = wid * 16 + (lane >> 2) + hr * 8;
#pragma unroll
        for (int nt = 0; nt < 4; nt++) {
            int col = nt * 8 + (lane & 3) * 2;
            float o0 = acc[nt][hr * 2 + 0] + b2[col];
            float o1 = acc[nt][hr * 2 + 1] + b2[col + 1];
            *(float2*)&out[((size_t)b * NN + n0 + row) * PP + col] = make_float2(o0, o1);
        }
    }
}

// ---------------- launch -----------------------------------------------------------
extern "C" void kernel_launch(void* const* d_in, const int* in_sizes, int n_in,
                              void* d_out, int out_size) {
    (void)in_sizes; (void)n_in; (void)out_size;
    const float* node_feats = (const float*)d_in[0];
    const float* z          = (const float*)d_in[1];
    const int*   children   = (const int*)  d_in[2];
    const float* conv1_w    = (const float*)d_in[3];
    const float* conv1_b    = (const float*)d_in[4];
    const float* conv2_w    = (const float*)d_in[5];
    const float* conv2_b    = (const float*)d_in[6];
    const float* mlp_w1     = (const float*)d_in[7];
    const float* mlp_b1     = (const float*)d_in[8];
    const float* mlp_w2     = (const float*)d_in[9];
    const float* mlp_b2     = (const float*)d_in[10];
    float* out = (float*)d_out;

    static bool attr_done = false;
    if (!attr_done) {
        cudaFuncSetAttribute(k_gemm<0>, cudaFuncAttributeMaxDynamicSharedMemorySize, GEMM_SMEM);
        cudaFuncSetAttribute(k_gemm<1>, cudaFuncAttributeMaxDynamicSharedMemorySize, GEMM_SMEM);
        cudaFuncSetAttribute(k_gemm<2>, cudaFuncAttributeMaxDynamicSharedMemorySize, GEMM_SMEM);
        cudaFuncSetAttribute(k_mlp2,    cudaFuncAttributeMaxDynamicSharedMemorySize, M2_SMEM);
        attr_done = true;
    }

    k_init<<<64, 256>>>();
    k_transpose<<<dim3(NN / 32, CC / 32, BB), dim3(32, 32)>>>(node_feats);
    k_pack<<<256, 256>>>(conv1_w, conv2_w, mlp_w1, mlp_w2);

    k_gemm<0><<<dim3(16, 2, BB), 256, GEMM_SMEM>>>(conv1_b, children, z);
    k_finalize<<<1, 64>>>(0);
    k_gemm<1><<<dim3(16, 2, BB), 256, GEMM_SMEM>>>(conv2_b, children, z);
    k_finalize<<<1, 64>>>(1);
    k_gemm<2><<<dim3(16, 2, BB), 256, GEMM_SMEM>>>(mlp_b1, children, z);

    k_mlp2<<<dim3(16, BB), 256, M2_SMEM>>>(mlp_b2, out);
}

// round 5
// speedup vs baseline: 3.6304x; 1.3121x over previous
#include <cuda_runtime.h>
#include <cuda_fp16.h>
#include <cstdint>
#include <math.h>

#define BB   64
#define CC   64
#define HH   256
#define LL   64
#define PP   32
#define NREAL 2047
#define NN   2048
#define KTOT 1280   // 192 (conv1) + 768 (conv2) + 320 (mlp1)

// ---------------- global scratch ---------------------------------------------
__device__ float  g_out1[(size_t)BB * NN * HH];
__device__ float  g_out2[(size_t)BB * NN * HH];
__device__ __align__(16) __half g_xtH [(size_t)BB * NN * CC];  // fp16 transposed input
__device__ __align__(16) __half g_wpHi[HH * KTOT];             // [h][k]
__device__ __align__(16) __half g_wpLo[HH * KTOT];
__device__ __align__(16) __half g_w2Hi[PP * HH];               // [p][k]
__device__ __align__(16) __half g_w2Lo[PP * HH];
__device__ double g_stats[2][BB][2];
__device__ float  g_norm [2][BB][2];

// ---------------- smem layouts (dynamic) ---------------------------------------
// k_gemm: A single plane x 2 stages; B hi/lo x 2 stages
#define GA_OFF   0                       // st*10240
#define GB_OFF   20480                   // (st*2+pl)*10240
#define GSIDX    61440
#define GRS      62976
#define GRSS     63008
#define GEMM_SMEM 63040
// k_mlp2: A 2 stages at 0; W2 planes at 20480 (pitch 528B)
#define M2A_OFF  0
#define M2W_OFF  20480
#define M2_SMEM  54272

// ---------------- helpers -------------------------------------------------------
__device__ __forceinline__ uint32_t smem_u32(const void* p) {
    uint32_t a;
    asm("{ .reg .u64 t; cvta.to.shared.u64 t, %1; cvt.u32.u64 %0, t; }" : "=r"(a) : "l"(p));
    return a;
}
__device__ __forceinline__ void ldm4(uint32_t* r, uint32_t addr) {
    asm volatile("ldmatrix.sync.aligned.m8n8.x4.shared.b16 {%0,%1,%2,%3}, [%4];"
                 : "=r"(r[0]), "=r"(r[1]), "=r"(r[2]), "=r"(r[3]) : "r"(addr));
}
__device__ __forceinline__ void mma16816(float* c, const uint32_t* a, uint32_t b0, uint32_t b1) {
    asm volatile("mma.sync.aligned.m16n8k16.row.col.f32.f16.f16.f32 "
                 "{%0,%1,%2,%3}, {%4,%5,%6,%7}, {%8,%9}, {%0,%1,%2,%3};"
                 : "+f"(c[0]), "+f"(c[1]), "+f"(c[2]), "+f"(c[3])
                 : "r"(a[0]), "r"(a[1]), "r"(a[2]), "r"(a[3]), "r"(b0), "r"(b1));
}
__device__ __forceinline__ void cp16(uint32_t dst, const void* src) {
    asm volatile("cp.async.ca.shared.global [%0], [%1], 16;" :: "r"(dst), "l"(src));
}
#define CP_COMMIT() asm volatile("cp.async.commit_group;" ::: "memory")
#define CP_WAIT0()  asm volatile("cp.async.wait_group 0;"  ::: "memory")
__device__ __forceinline__ uint32_t pkh(__half a, __half b) {
    return (uint32_t)__half_as_ushort(a) | ((uint32_t)__half_as_ushort(b) << 16);
}

// ---------------- init -----------------------------------------------------------
__global__ void k_init() {
    int t = blockIdx.x * blockDim.x + threadIdx.x;
    if (t < 2 * BB * 2) ((double*)g_stats)[t] = 0.0;
    for (int i = t; i < BB * HH; i += gridDim.x * blockDim.x) {
        int b = i >> 8, h = i & 255;
        g_out1[(size_t)b * NN * HH + h] = 0.f;
        g_out2[(size_t)b * NN * HH + h] = 0.f;
    }
}

// ---------------- transpose node_feats [B,C,N] -> fp16 [B,N,C] ---------------------
__global__ void k_transpose(const float* __restrict__ x) {
    __shared__ float tile[32][33];
    int b  = blockIdx.z;
    int n0 = blockIdx.x * 32;
    int c0 = blockIdx.y * 32;
    int tx = threadIdx.x, ty = threadIdx.y;
    tile[ty][tx] = x[((size_t)b * CC + c0 + ty) * NN + n0 + tx];
    __syncthreads();
    g_xtH[((size_t)b * NN + n0 + ty) * CC + c0 + tx] = __float2half(tile[tx][ty]);
}

// ---------------- pack weights into fp16 hi/lo -------------------------------------
__global__ void k_pack(const float* __restrict__ w1c, const float* __restrict__ w2c,
                       const float* __restrict__ wm, const float* __restrict__ wm2) {
    int t = blockIdx.x * blockDim.x + threadIdx.x;
    int stride = gridDim.x * blockDim.x;
    for (int e = t; e < HH * KTOT; e += stride) {
        int h = e / KTOT, k = e % KTOT;
        float w;
        if (k < 192)      { int j = k / 64,  c = k % 64;            w = w1c[(h * CC + c) * 3 + j]; }
        else if (k < 960) { int kk = k - 192; int j = kk / 256, c = kk % 256; w = w2c[(h * HH + c) * 3 + j]; }
        else              { int kk = k - 960; w = wm[kk * HH + h]; }
        __half hi = __float2half(w);
        g_wpHi[e] = hi;
        g_wpLo[e] = __float2half(w - __half2float(hi));
    }
    for (int e = t; e < PP * HH; e += stride) {
        int p = e >> 8, k = e & 255;
        float w = wm2[k * PP + p];
        __half hi = __float2half(w);
        g_w2Hi[e] = hi;
        g_w2Lo[e] = __float2half(w - __half2float(hi));
    }
}

// ---------------- fused gather + mma.sync GEMM (fp16, 2-product) -------------------
// STAGE 0: conv1 src=g_xtH fp16 (CIN=64, K=192, cp.async gather)   -> g_out1 + stats0
// STAGE 1: conv2 src=g_out1 fp32 (CIN=256, K=768, gather,norm+relu)-> g_out2 + stats1
// STAGE 2: mlp1  src=g_out2 (K=320: 256 norm+relu, 64 z)           -> relu -> g_out1
template <int STAGE>
__global__ void __launch_bounds__(256, 2) k_gemm(const float* __restrict__ bias,
                                                 const int* __restrict__ children,
                                                 const float* __restrict__ zin) {
    extern __shared__ __align__(16) char smem[];
    constexpr int CIN   = (STAGE == 0) ? 64 : 256;
    constexpr int NCH   = (STAGE == 0) ? 6 : (STAGE == 1) ? 24 : 10;
    constexpr int KBASE = (STAGE == 0) ? 0 : (STAGE == 1) ? 192 : 960;

    const int tile = blockIdx.x, hb = blockIdx.y, b = blockIdx.z;
    const int h0   = hb * 128;
    const int nbase = (STAGE == 2) ? tile * 128 : 1 + tile * 128;
    const int tid = threadIdx.x, lane = tid & 31, wid = tid >> 5;
    const int wm = wid & 3, wn = wid >> 2;
    const uint32_t sb = smem_u32(smem);
    int* sidx = (int*)(smem + GSIDX);

    float mean = 0.f, istd = 1.f;
    if (STAGE >= 1) { mean = g_norm[STAGE - 1][b][0]; istd = g_norm[STAGE - 1][b][1]; }

    if (STAGE < 2) {
        for (int i = tid; i < 384; i += 256) {
            int gn = nbase + i / 3;
            sidx[i] = (gn <= NREAL) ? children[b * 3 * NREAL + (gn - 1) * 3 + (i % 3)] : 0;
        }
        __syncthreads();
    }

    const float* srcb = ((STAGE == 1) ? g_out1 : g_out2) + (size_t)b * NN * HH;
    const __half* xtb = g_xtH + (size_t)b * NN * CC;
    const int m = tid >> 1, half_ = tid & 1;

    float acc[2][8][4];
#pragma unroll
    for (int mt = 0; mt < 2; mt++)
#pragma unroll
        for (int nt = 0; nt < 8; nt++)
#pragma unroll
            for (int q = 0; q < 4; q++) acc[mt][nt][q] = 0.f;

    // ---- producers ----
    auto copyB = [&](int qc, int st) {
        const int kofs = KBASE + qc * 32;
#pragma unroll
        for (int pl = 0; pl < 2; ++pl) {
            const __half* gw = (pl ? g_wpLo : g_wpHi);
            uint32_t dbase = sb + GB_OFF + (uint32_t)(st * 2 + pl) * 10240u;
#pragma unroll
            for (int u = 0; u < 2; ++u) {
                int seg = tid + u * 256;
                int row = seg >> 2, s4 = seg & 3;
                cp16(dbase + (uint32_t)row * 80u + (uint32_t)s4 * 16u,
                     gw + (size_t)(h0 + row) * KTOT + kofs + s4 * 8);
            }
        }
    };
    // STAGE 0 only: direct cp.async gather of fp16 A
    auto copyA0 = [&](int qc, int st) {
        const int j = qc >> 1, c0 = (qc & 1) * 32;
        const int r = tid >> 1, sg2 = (tid & 1) * 2;
        int idx = sidx[r * 3 + j];
        const __half* src = xtb + (size_t)idx * CC + c0 + sg2 * 8;
        uint32_t dst = sb + GA_OFF + (uint32_t)st * 10240u + (uint32_t)r * 80u + (uint32_t)sg2 * 16u;
        cp16(dst, src);
        cp16(dst + 16, src + 8);
    };
    // STAGES 1,2: register gather + norm + fp16 convert
    auto loadA = [&](int qc, float4* av) {
        int j = 0, c0 = 0;
        if (STAGE == 1) { j = qc >> 3; c0 = (qc & 7) * 32; }
        else            { c0 = qc * 32; }
        if (STAGE == 2 && c0 >= 256) {
            const float4* zp = (const float4*)(zin + b * LL + (c0 - 256) + half_ * 16);
#pragma unroll
            for (int f = 0; f < 4; f++) av[f] = zp[f];
        } else {
            int row = (STAGE == 2) ? (nbase + m) : sidx[m * 3 + j];
            const float4* p = (const float4*)(srcb + (size_t)row * HH + c0 + half_ * 16);
#pragma unroll
            for (int f = 0; f < 4; f++) av[f] = p[f];
#pragma unroll
            for (int f = 0; f < 4; f++) {
                av[f].x = fmaxf((av[f].x - mean) * istd, 0.f);
                av[f].y = fmaxf((av[f].y - mean) * istd, 0.f);
                av[f].z = fmaxf((av[f].z - mean) * istd, 0.f);
                av[f].w = fmaxf((av[f].w - mean) * istd, 0.f);
            }
        }
    };
    auto cvtStsA = [&](const float4* av, int st) {
        uint32_t hi[8];
#pragma unroll
        for (int f = 0; f < 4; f++) {
            hi[2 * f]     = pkh(__float2half(av[f].x), __float2half(av[f].y));
            hi[2 * f + 1] = pkh(__float2half(av[f].z), __float2half(av[f].w));
        }
        char* aH = smem + GA_OFF + st * 10240 + m * 80 + half_ * 32;
        *(uint4*)(aH)      = make_uint4(hi[0], hi[1], hi[2], hi[3]);
        *(uint4*)(aH + 16) = make_uint4(hi[4], hi[5], hi[6], hi[7]);
    };

    // ---- prologue ----
    float4 av[4];
    copyB(0, 0);
    if (STAGE == 0) {
        copyA0(0, 0);
        CP_COMMIT();
    } else {
        CP_COMMIT();
        loadA(0, av);
        cvtStsA(av, 0);
    }
    CP_WAIT0();
    __syncthreads();

    // ---- main loop: one sync per chunk ----
    for (int qc = 0; qc < NCH; ++qc) {
        const int cst = qc & 1, nst = cst ^ 1;
        const bool more = (qc + 1 < NCH);
        if (more) {
            copyB(qc + 1, nst);
            if (STAGE == 0) copyA0(qc + 1, nst);
            CP_COMMIT();
            if (STAGE != 0) loadA(qc + 1, av);
        }
        const uint32_t aB = sb + GA_OFF + (uint32_t)cst * 10240u;
        const uint32_t bH = sb + GB_OFF + (uint32_t)(cst * 2) * 10240u;
        const uint32_t bL = bH + 10240u;
#pragma unroll
        for (int s = 0; s < 2; s++) {
            const uint32_t colB = (uint32_t)(s * 16 + (lane >> 4) * 8) * 2u;
            const uint32_t arow = (uint32_t)(wm * 32 + (lane & 15)) * 80u;
            uint32_t af[2][4];
            ldm4(af[0], aB + arow + colB);
            ldm4(af[1], aB + arow + 16 * 80 + colB);
            const uint32_t brow = (uint32_t)(wn * 64 + (lane & 15)) * 80u;
#pragma unroll
            for (int jp = 0; jp < 4; jp++) {
                uint32_t rh[4], rl[4];
                ldm4(rh, bH + brow + (uint32_t)jp * 16 * 80 + colB);
                ldm4(rl, bL + brow + (uint32_t)jp * 16 * 80 + colB);
#pragma unroll
                for (int mt = 0; mt < 2; mt++) {
                    mma16816(acc[mt][2 * jp],     af[mt], rh[0], rh[2]);
                    mma16816(acc[mt][2 * jp],     af[mt], rl[0], rl[2]);
                    mma16816(acc[mt][2 * jp + 1], af[mt], rh[1], rh[3]);
                    mma16816(acc[mt][2 * jp + 1], af[mt], rl[1], rl[3]);
                }
            }
        }
        if (more && STAGE != 0) cvtStsA(av, nst);
        CP_WAIT0();
        __syncthreads();
    }

    // ---- epilogue: bias (+relu), store fp32, stats ----
    float* dst = (STAGE == 1) ? g_out2 : g_out1;
    float s = 0.f, ss = 0.f;
#pragma unroll
    for (int mt = 0; mt < 2; mt++) {
#pragma unroll
        for (int hr = 0; hr < 2; hr++) {
            int rrow = wm * 32 + mt * 16 + (lane >> 2) + hr * 8;
            int gn   = nbase + rrow;
            bool valid = (STAGE == 2) || (gn <= NREAL);
            if (valid) {
                float* drow = dst + ((size_t)b * NN + gn) * HH;
#pragma unroll
                for (int nt = 0; nt < 8; nt++) {
                    int col = h0 + wn * 64 + nt * 8 + (lane & 3) * 2;
                    float o0 = acc[mt][nt][hr * 2 + 0] + bias[col];
                    float o1 = acc[mt][nt][hr * 2 + 1] + bias[col + 1];
                    if (STAGE == 2) { o0 = fmaxf(o0, 0.f); o1 = fmaxf(o1, 0.f); }
                    *(float2*)&drow[col] = make_float2(o0, o1);
                    if (STAGE != 2) { s += o0 + o1; ss += o0 * o0 + o1 * o1; }
                }
            }
        }
    }
    if (STAGE != 2) {
#pragma unroll
        for (int off = 16; off > 0; off >>= 1) {
            s  += __shfl_down_sync(0xffffffffu, s,  off);
            ss += __shfl_down_sync(0xffffffffu, ss, off);
        }
        float* rs  = (float*)(smem + GRS);
        float* rss = (float*)(smem + GRSS);
        if (lane == 0) { rs[wid] = s; rss[wid] = ss; }
        __syncthreads();
        if (tid == 0) {
            float S = 0.f, SS = 0.f;
#pragma unroll
            for (int w = 0; w < 8; w++) { S += rs[w]; SS += rss[w]; }
            atomicAdd(&g_stats[STAGE][b][0], (double)S);
            atomicAdd(&g_stats[STAGE][b][1], (double)SS);
        }
    }
}

// ---------------- finalize norm stats ------------------------------------------
__global__ void k_finalize(int stage) {
    int b = threadIdx.x;
    if (b < BB) {
        double s  = g_stats[stage][b][0];
        double ss = g_stats[stage][b][1];
        const double cnt = (double)HH * (double)NN;
        double mean = s / cnt;
        double var  = (ss - s * s / cnt) / (cnt - 1.0);
        if (var < 0.0) var = 0.0;
        double sd = sqrt(var) + 1e-5;
        g_norm[stage][b][0] = (float)mean;
        g_norm[stage][b][1] = (float)(1.0 / sd);
    }
}

// ---------------- MLP layer 2 via mma (fp16 2-product) --------------------------
__global__ void __launch_bounds__(256, 2) k_mlp2(const float* __restrict__ b2,
                                                 float* __restrict__ out) {
    extern __shared__ __align__(16) char smem[];
    const int b   = blockIdx.y;
    const int n0  = blockIdx.x * 128;
    const int tid = threadIdx.x, lane = tid & 31, wid = tid >> 5;
    const uint32_t sb = smem_u32(smem);
    const int m = tid >> 1, half_ = tid & 1;

    // load W2 planes: [32 p][256 k], pitch 528 B
#pragma unroll
    for (int pl = 0; pl < 2; ++pl) {
        const __half* gw = (pl ? g_w2Lo : g_w2Hi);
        char* dbase = smem + M2W_OFF + pl * 16896;
#pragma unroll
        for (int u = 0; u < 4; ++u) {
            int seg = tid + u * 256;
            int row = seg >> 5, s16 = seg & 31;
            *(uint4*)(dbase + row * 528 + s16 * 16) = *(const uint4*)(gw + row * 256 + s16 * 8);
        }
    }

    const float* srcb = g_out1 + ((size_t)b * NN + n0) * HH;

    float acc[4][4];
#pragma unroll
    for (int nt = 0; nt < 4; nt++)
#pragma unroll
        for (int q = 0; q < 4; q++) acc[nt][q] = 0.f;

    auto loadA = [&](int qc, float4* av) {
        const float4* p = (const float4*)(srcb + (size_t)m * HH + qc * 32 + half_ * 16);
#pragma unroll
        for (int f = 0; f < 4; f++) av[f] = p[f];
    };
    auto cvtStsA = [&](const float4* av, int st) {
        uint32_t hi[8];
#pragma unroll
        for (int f = 0; f < 4; f++) {
            hi[2 * f]     = pkh(__float2half(av[f].x), __float2half(av[f].y));
            hi[2 * f + 1] = pkh(__float2half(av[f].z), __float2half(av[f].w));
        }
        char* aH = smem + M2A_OFF + st * 10240 + m * 80 + half_ * 32;
        *(uint4*)(aH)      = make_uint4(hi[0], hi[1], hi[2], hi[3]);
        *(uint4*)(aH + 16) = make_uint4(hi[4], hi[5], hi[6], hi[7]);
    };

    float4 av[4];
    loadA(0, av);
    cvtStsA(av, 0);
    __syncthreads();

    const uint32_t w2H = sb + M2W_OFF;
    const uint32_t w2L = w2H + 16896u;

    for (int qc = 0; qc < 8; ++qc) {
        const int cst = qc & 1, nst = cst ^ 1;
        const bool more = (qc + 1 < 8);
        if (more) loadA(qc + 1, av);
        const uint32_t aB = sb + M2A_OFF + (uint32_t)cst * 10240u;
#pragma unroll
        for (int s = 0; s < 2; s++) {
            const uint32_t colB = (uint32_t)(s * 16 + (lane >> 4) * 8) * 2u;
            const uint32_t arow = (uint32_t)(wid * 16 + (lane & 15)) * 80u;
            uint32_t af[4];
            ldm4(af, aB + arow + colB);
            const uint32_t kbyte = (uint32_t)(qc * 32) * 2u + colB;
#pragma unroll
            for (int ng = 0; ng < 2; ng++) {
                const uint32_t brow = (uint32_t)(ng * 16 + (lane & 15)) * 528u;
                uint32_t rh[4], rl[4];
                ldm4(rh, w2H + brow + kbyte);
                ldm4(rl, w2L + brow + kbyte);
                mma16816(acc[ng * 2],     af, rh[0], rh[2]);
                mma16816(acc[ng * 2],     af, rl[0], rl[2]);
                mma16816(acc[ng * 2 + 1], af, rh[1], rh[3]);
                mma16816(acc[ng * 2 + 1], af, rl[1], rl[3]);
            }
        }
        if (more) cvtStsA(av, nst);
        __syncthreads();
    }

    // epilogue
#pragma unroll
    for (int hr = 0; hr < 2; hr++) {
        int row = wid * 16 + (lane >> 2) + hr * 8;
#pragma unroll
        for (int nt = 0; nt < 4; nt++) {
            int col = nt * 8 + (lane & 3) * 2;
            float o0 = acc[nt][hr * 2 + 0] + b2[col];
            float o1 = acc[nt][hr * 2 + 1] + b2[col + 1];
            *(float2*)&out[((size_t)b * NN + n0 + row) * PP + col] = make_float2(o0, o1);
        }
    }
}

// ---------------- launch -----------------------------------------------------------
extern "C" void kernel_launch(void* const* d_in, const int* in_sizes, int n_in,
                              void* d_out, int out_size) {
    (void)in_sizes; (void)n_in; (void)out_size;
    const float* node_feats = (const float*)d_in[0];
    const float* z          = (const float*)d_in[1];
    const int*   children   = (const int*)  d_in[2];
    const float* conv1_w    = (const float*)d_in[3];
    const float* conv1_b    = (const float*)d_in[4];
    const float* conv2_w    = (const float*)d_in[5];
    const float* conv2_b    = (const float*)d_in[6];
    const float* mlp_w1     = (const float*)d_in[7];
    const float* mlp_b1     = (const float*)d_in[8];
    const float* mlp_w2     = (const float*)d_in[9];
    const float* mlp_b2     = (const float*)d_in[10];
    float* out = (float*)d_out;

    static bool attr_done = false;
    if (!attr_done) {
        cudaFuncSetAttribute(k_gemm<0>, cudaFuncAttributeMaxDynamicSharedMemorySize, GEMM_SMEM);
        cudaFuncSetAttribute(k_gemm<1>, cudaFuncAttributeMaxDynamicSharedMemorySize, GEMM_SMEM);
        cudaFuncSetAttribute(k_gemm<2>, cudaFuncAttributeMaxDynamicSharedMemorySize, GEMM_SMEM);
        cudaFuncSetAttribute(k_mlp2,    cudaFuncAttributeMaxDynamicSharedMemorySize, M2_SMEM);
        attr_done = true;
    }

    k_init<<<64, 256>>>();
    k_transpose<<<dim3(NN / 32, CC / 32, BB), dim3(32, 32)>>>(node_feats);
    k_pack<<<256, 256>>>(conv1_w, conv2_w, mlp_w1, mlp_w2);

    k_gemm<0><<<dim3(16, 2, BB), 256, GEMM_SMEM>>>(conv1_b, children, z);
    k_finalize<<<1, 64>>>(0);
    k_gemm<1><<<dim3(16, 2, BB), 256, GEMM_SMEM>>>(conv2_b, children, z);
    k_finalize<<<1, 64>>>(1);
    k_gemm<2><<<dim3(16, 2, BB), 256, GEMM_SMEM>>>(mlp_b1, children, z);

    k_mlp2<<<dim3(16, BB), 256, M2_SMEM>>>(mlp_b2, out);
}

// round 6
// speedup vs baseline: 3.9438x; 1.0863x over previous
#include <cuda_runtime.h>
#include <cuda_fp16.h>
#include <cstdint>
#include <math.h>

#define BB   64
#define CC   64
#define HH   256
#define LL   64
#define PP   32
#define NREAL 2047
#define NN   2048
#define KTOT 1280   // 192 (conv1) + 768 (conv2) + 320 (mlp1)

// ---------------- global scratch ---------------------------------------------
__device__ __align__(16) __half g_xtH [(size_t)BB * NN * CC];  // fp16 transposed input
__device__ __align__(16) __half g_buf1[(size_t)BB * NN * HH];  // conv1 out, later mlp1 out
__device__ __align__(16) __half g_buf2[(size_t)BB * NN * HH];  // conv2 out
__device__ __align__(16) __half g_wpHi[HH * KTOT];             // [h][k]
__device__ __align__(16) __half g_wpLo[HH * KTOT];
__device__ __align__(16) __half g_w2Hi[PP * HH];               // [p][k]
__device__ __align__(16) __half g_w2Lo[PP * HH];
__device__ double g_stats[2][BB][2];
__device__ float  g_norm [2][BB][2];

// ---------------- smem layouts (dynamic) ---------------------------------------
#define GA_OFF   0                       // st*10240
#define GB_OFF   20480                   // (st*2+pl)*10240
#define GSIDX    61440
#define GRS      62976
#define GRSS     63040
#define GBIAS    63104                   // 128 floats
#define GEMM_SMEM 63616
// k_mlp2: A 2 stages at 0; W2 planes at 20480 (pitch 528B)
#define M2A_OFF  0
#define M2W_OFF  20480
#define M2_SMEM  54272

// ---------------- helpers -------------------------------------------------------
__device__ __forceinline__ uint32_t smem_u32(const void* p) {
    uint32_t a;
    asm("{ .reg .u64 t; cvta.to.shared.u64 t, %1; cvt.u32.u64 %0, t; }" : "=r"(a) : "l"(p));
    return a;
}
__device__ __forceinline__ void ldm4(uint32_t* r, uint32_t addr) {
    asm volatile("ldmatrix.sync.aligned.m8n8.x4.shared.b16 {%0,%1,%2,%3}, [%4];"
                 : "=r"(r[0]), "=r"(r[1]), "=r"(r[2]), "=r"(r[3]) : "r"(addr));
}
__device__ __forceinline__ void mma16816(float* c, const uint32_t* a, uint32_t b0, uint32_t b1) {
    asm volatile("mma.sync.aligned.m16n8k16.row.col.f32.f16.f16.f32 "
                 "{%0,%1,%2,%3}, {%4,%5,%6,%7}, {%8,%9}, {%0,%1,%2,%3};"
                 : "+f"(c[0]), "+f"(c[1]), "+f"(c[2]), "+f"(c[3])
                 : "r"(a[0]), "r"(a[1]), "r"(a[2]), "r"(a[3]), "r"(b0), "r"(b1));
}
__device__ __forceinline__ void cp16(uint32_t dst, const void* src) {
    asm volatile("cp.async.cg.shared.global [%0], [%1], 16;" :: "r"(dst), "l"(src));
}
#define CP_COMMIT() asm volatile("cp.async.commit_group;" ::: "memory")
#define CP_WAIT0()  asm volatile("cp.async.wait_group 0;"  ::: "memory")
__device__ __forceinline__ uint32_t pkh(__half a, __half b) {
    return (uint32_t)__half_as_ushort(a) | ((uint32_t)__half_as_ushort(b) << 16);
}
__device__ __forceinline__ uint32_t pkf(float a, float b) {
    return pkh(__float2half(a), __float2half(b));
}

// ---------------- init -----------------------------------------------------------
__global__ void k_init() {
    int t = blockIdx.x * blockDim.x + threadIdx.x;
    if (t < 2 * BB * 2) ((double*)g_stats)[t] = 0.0;
    for (int i = t; i < BB * HH; i += gridDim.x * blockDim.x) {
        int b = i >> 8, h = i & 255;
        g_buf1[(size_t)b * NN * HH + h] = __float2half(0.f);
        g_buf2[(size_t)b * NN * HH + h] = __float2half(0.f);
    }
}

// ---------------- transpose node_feats [B,C,N] -> fp16 [B,N,C] ---------------------
__global__ void k_transpose(const float* __restrict__ x) {
    __shared__ float tile[32][33];
    int b  = blockIdx.z;
    int n0 = blockIdx.x * 32;
    int c0 = blockIdx.y * 32;
    int tx = threadIdx.x, ty = threadIdx.y;
    tile[ty][tx] = x[((size_t)b * CC + c0 + ty) * NN + n0 + tx];
    __syncthreads();
    g_xtH[((size_t)b * NN + n0 + ty) * CC + c0 + tx] = __float2half(tile[tx][ty]);
}

// ---------------- pack weights into fp16 hi/lo -------------------------------------
__global__ void k_pack(const float* __restrict__ w1c, const float* __restrict__ w2c,
                       const float* __restrict__ wm, const float* __restrict__ wm2) {
    int t = blockIdx.x * blockDim.x + threadIdx.x;
    int stride = gridDim.x * blockDim.x;
    for (int e = t; e < HH * KTOT; e += stride) {
        int h = e / KTOT, k = e % KTOT;
        float w;
        if (k < 192)      { int j = k / 64,  c = k % 64;            w = w1c[(h * CC + c) * 3 + j]; }
        else if (k < 960) { int kk = k - 192; int j = kk / 256, c = kk % 256; w = w2c[(h * HH + c) * 3 + j]; }
        else              { int kk = k - 960; w = wm[kk * HH + h]; }
        __half hi = __float2half(w);
        g_wpHi[e] = hi;
        g_wpLo[e] = __float2half(w - __half2float(hi));
    }
    for (int e = t; e < PP * HH; e += stride) {
        int p = e >> 8, k = e & 255;
        float w = wm2[k * PP + p];
        __half hi = __float2half(w);
        g_w2Hi[e] = hi;
        g_w2Lo[e] = __float2half(w - __half2float(hi));
    }
}

// ---------------- fused gather + mma.sync GEMM (fp16 in/out, 2-product B) ----------
// STAGE 0: conv1 src=g_xtH (K=192, cp.async gather)            -> g_buf1 + stats0
// STAGE 1: conv2 src=g_buf1 (K=768, gather + norm0 + relu)     -> g_buf2 + stats1
// STAGE 2: mlp1  src=g_buf2 (K=320: 256 norm1+relu, 64 z)      -> relu -> g_buf1
// CTA 256 thr, tile 128M x 128N. Warp grid 2M x 4N (warp tile 64x32).
template <int STAGE>
__global__ void __launch_bounds__(256, 2) k_gemm(const float* __restrict__ bias,
                                                 const int* __restrict__ children,
                                                 const float* __restrict__ zin) {
    extern __shared__ __align__(16) char smem[];
    constexpr int NCH   = (STAGE == 0) ? 6 : (STAGE == 1) ? 24 : 10;
    constexpr int KBASE = (STAGE == 0) ? 0 : (STAGE == 1) ? 192 : 960;

    const int tile = blockIdx.x, hb = blockIdx.y, b = blockIdx.z;
    const int h0   = hb * 128;
    const int nbase = (STAGE == 2) ? tile * 128 : 1 + tile * 128;
    const int tid = threadIdx.x, lane = tid & 31, wid = tid >> 5;
    const int wm = wid & 1, wn = wid >> 1;
    const uint32_t sb = smem_u32(smem);
    int* sidx = (int*)(smem + GSIDX);

    float mean = 0.f, istd = 1.f;
    if (STAGE >= 1) { mean = g_norm[STAGE - 1][b][0]; istd = g_norm[STAGE - 1][b][1]; }

    if (tid < 128) ((float*)(smem + GBIAS))[tid] = bias[h0 + tid];
    if (STAGE < 2) {
        for (int i = tid; i < 384; i += 256) {
            int gn = nbase + i / 3;
            sidx[i] = (gn <= NREAL) ? children[b * 3 * NREAL + (gn - 1) * 3 + (i % 3)] : 0;
        }
    }
    __syncthreads();

    const __half* srcb = ((STAGE == 1) ? g_buf1 : g_buf2) + (size_t)b * NN * HH;
    const __half* xtb  = g_xtH + (size_t)b * NN * CC;
    const int m = tid >> 1, half_ = tid & 1;

    float acc[4][4][4];
#pragma unroll
    for (int mt = 0; mt < 4; mt++)
#pragma unroll
        for (int nt = 0; nt < 4; nt++)
#pragma unroll
            for (int q = 0; q < 4; q++) acc[mt][nt][q] = 0.f;

    // ---- producers ----
    auto copyB = [&](int qc, int st) {
        const int kofs = KBASE + qc * 32;
#pragma unroll
        for (int pl = 0; pl < 2; ++pl) {
            const __half* gw = (pl ? g_wpLo : g_wpHi);
            uint32_t dbase = sb + GB_OFF + (uint32_t)(st * 2 + pl) * 10240u;
#pragma unroll
            for (int u = 0; u < 2; ++u) {
                int seg = tid + u * 256;
                int row = seg >> 2, s4 = seg & 3;
                cp16(dbase + (uint32_t)row * 80u + (uint32_t)s4 * 16u,
                     gw + (size_t)(h0 + row) * KTOT + kofs + s4 * 8);
            }
        }
    };
    // STAGE 0: direct cp.async gather of fp16 A
    auto copyA0 = [&](int qc, int st) {
        const int j = qc >> 1, c0 = (qc & 1) * 32;
        const int r = tid >> 1, sg2 = (tid & 1) * 2;
        int idx = sidx[r * 3 + j];
        const __half* src = xtb + (size_t)idx * CC + c0 + sg2 * 8;
        uint32_t dst = sb + GA_OFF + (uint32_t)st * 10240u + (uint32_t)r * 80u + (uint32_t)sg2 * 16u;
        cp16(dst, src);
        cp16(dst + 16, src + 8);
    };
    // STAGES 1,2: fp16 gather + norm + relu, packed to 8 uint32 (16 halfs)
    auto loadA = [&](int qc, uint32_t* hi) {
        int j = 0, c0 = 0;
        if (STAGE == 1) { j = qc >> 3; c0 = (qc & 7) * 32; }
        else            { c0 = qc * 32; }
        if (STAGE == 2 && c0 >= 256) {
            const float4* zp = (const float4*)(zin + b * LL + (c0 - 256) + half_ * 16);
#pragma unroll
            for (int f = 0; f < 4; f++) {
                float4 v = zp[f];
                hi[2 * f]     = pkf(v.x, v.y);
                hi[2 * f + 1] = pkf(v.z, v.w);
            }
        } else {
            int row = (STAGE == 2) ? (nbase + m) : sidx[m * 3 + j];
            const uint4* p = (const uint4*)(srcb + (size_t)row * HH + c0 + half_ * 16);
            uint4 v0 = p[0], v1 = p[1];
            const uint32_t* vv = (const uint32_t*)&v0;
#pragma unroll
            for (int f = 0; f < 8; f++) {
                uint32_t w = (f < 4) ? vv[f] : ((const uint32_t*)&v1)[f - 4];
                float2 fv = __half22float2(*(const __half2*)&w);
                fv.x = fmaxf((fv.x - mean) * istd, 0.f);
                fv.y = fmaxf((fv.y - mean) * istd, 0.f);
                hi[f] = pkf(fv.x, fv.y);
            }
        }
    };
    auto stsA = [&](const uint32_t* hi, int st) {
        char* aH = smem + GA_OFF + st * 10240 + m * 80 + half_ * 32;
        *(uint4*)(aH)      = make_uint4(hi[0], hi[1], hi[2], hi[3]);
        *(uint4*)(aH + 16) = make_uint4(hi[4], hi[5], hi[6], hi[7]);
    };

    // ---- prologue ----
    uint32_t areg[8];
    copyB(0, 0);
    if (STAGE == 0) {
        copyA0(0, 0);
        CP_COMMIT();
    } else {
        CP_COMMIT();
        loadA(0, areg);
        stsA(areg, 0);
    }
    CP_WAIT0();
    __syncthreads();

    // ---- main loop ----
#pragma unroll 2
    for (int qc = 0; qc < NCH; ++qc) {
        const int cst = qc & 1, nst = cst ^ 1;
        const bool more = (qc + 1 < NCH);
        if (more) {
            copyB(qc + 1, nst);
            if (STAGE == 0) copyA0(qc + 1, nst);
            CP_COMMIT();
            if (STAGE != 0) loadA(qc + 1, areg);
        }
        const uint32_t aB = sb + GA_OFF + (uint32_t)cst * 10240u;
        const uint32_t bH = sb + GB_OFF + (uint32_t)(cst * 2) * 10240u;
        const uint32_t bL = bH + 10240u;
#pragma unroll
        for (int s = 0; s < 2; s++) {
            const uint32_t colB = (uint32_t)(s * 16 + (lane >> 4) * 8) * 2u;
            uint32_t af[4][4];
            const uint32_t arow = (uint32_t)(wm * 64 + (lane & 15)) * 80u;
#pragma unroll
            for (int mt = 0; mt < 4; mt++)
                ldm4(af[mt], aB + arow + (uint32_t)mt * (16 * 80) + colB);
#pragma unroll
            for (int pl = 0; pl < 2; pl++) {
                const uint32_t bb = pl ? bL : bH;
#pragma unroll
                for (int ng = 0; ng < 2; ng++) {
                    uint32_t rb[4];
                    const uint32_t brow = (uint32_t)(wn * 32 + ng * 16 + (lane & 15)) * 80u;
                    ldm4(rb, bb + brow + colB);
#pragma unroll
                    for (int mt = 0; mt < 4; mt++) {
                        mma16816(acc[mt][ng * 2 + 0], af[mt], rb[0], rb[2]);
                        mma16816(acc[mt][ng * 2 + 1], af[mt], rb[1], rb[3]);
                    }
                }
            }
        }
        if (more && STAGE != 0) stsA(areg, nst);
        CP_WAIT0();
        __syncthreads();
    }

    // ---- epilogue: bias (+relu), fp16 store, stats ----
    __half* dst = (STAGE == 1) ? g_buf2 : g_buf1;
    const float* sBias = (const float*)(smem + GBIAS);
    float s = 0.f, ss = 0.f;
#pragma unroll
    for (int mt = 0; mt < 4; mt++) {
#pragma unroll
        for (int hr = 0; hr < 2; hr++) {
            int rrow = wm * 64 + mt * 16 + (lane >> 2) + hr * 8;
            int gn   = nbase + rrow;
            bool valid = (STAGE == 2) || (gn <= NREAL);
            if (valid) {
                __half* drow = dst + ((size_t)b * NN + gn) * HH + h0;
#pragma unroll
                for (int nt = 0; nt < 4; nt++) {
                    int col = wn * 32 + nt * 8 + (lane & 3) * 2;
                    float o0 = acc[mt][nt][hr * 2 + 0] + sBias[col];
                    float o1 = acc[mt][nt][hr * 2 + 1] + sBias[col + 1];
                    if (STAGE == 2) { o0 = fmaxf(o0, 0.f); o1 = fmaxf(o1, 0.f); }
                    *(uint32_t*)&drow[col] = pkf(o0, o1);
                    if (STAGE != 2) { s += o0 + o1; ss += o0 * o0 + o1 * o1; }
                }
            }
        }
    }
    if (STAGE != 2) {
#pragma unroll
        for (int off = 16; off > 0; off >>= 1) {
            s  += __shfl_down_sync(0xffffffffu, s,  off);
            ss += __shfl_down_sync(0xffffffffu, ss, off);
        }
        float* rs  = (float*)(smem + GRS);
        float* rss = (float*)(smem + GRSS);
        if (lane == 0) { rs[wid] = s; rss[wid] = ss; }
        __syncthreads();
        if (tid == 0) {
            float S = 0.f, SS = 0.f;
#pragma unroll
            for (int w = 0; w < 8; w++) { S += rs[w]; SS += rss[w]; }
            atomicAdd(&g_stats[STAGE][b][0], (double)S);
            atomicAdd(&g_stats[STAGE][b][1], (double)SS);
        }
    }
}

// ---------------- finalize norm stats ------------------------------------------
__global__ void k_finalize(int stage) {
    int b = threadIdx.x;
    if (b < BB) {
        double s  = g_stats[stage][b][0];
        double ss = g_stats[stage][b][1];
        const double cnt = (double)HH * (double)NN;
        double mean = s / cnt;
        double var  = (ss - s * s / cnt) / (cnt - 1.0);
        if (var < 0.0) var = 0.0;
        double sd = sqrt(var) + 1e-5;
        g_norm[stage][b][0] = (float)mean;
        g_norm[stage][b][1] = (float)(1.0 / sd);
    }
}

// ---------------- MLP layer 2 via mma (fp16 A by cp.async) -----------------------
__global__ void __launch_bounds__(256, 2) k_mlp2(const float* __restrict__ b2,
                                                 float* __restrict__ out) {
    extern __shared__ __align__(16) char smem[];
    const int b   = blockIdx.y;
    const int n0  = blockIdx.x * 128;
    const int tid = threadIdx.x, lane = tid & 31, wid = tid >> 5;
    const uint32_t sb = smem_u32(smem);

    // load W2 planes: [32 p][256 k], pitch 528 B
#pragma unroll
    for (int pl = 0; pl < 2; ++pl) {
        const __half* gw = (pl ? g_w2Lo : g_w2Hi);
        char* dbase = smem + M2W_OFF + pl * 16896;
#pragma unroll
        for (int u = 0; u < 4; ++u) {
            int seg = tid + u * 256;
            int row = seg >> 5, s16 = seg & 31;
            *(uint4*)(dbase + row * 528 + s16 * 16) = *(const uint4*)(gw + row * 256 + s16 * 8);
        }
    }

    const __half* srcb = g_buf1 + ((size_t)b * NN + n0) * HH;
    const int r = tid >> 1, sg2 = (tid & 1) * 2;

    float acc[4][4];
#pragma unroll
    for (int nt = 0; nt < 4; nt++)
#pragma unroll
        for (int q = 0; q < 4; q++) acc[nt][q] = 0.f;

    auto copyA = [&](int qc, int st) {
        const __half* src = srcb + (size_t)r * HH + qc * 32 + sg2 * 8;
        uint32_t dst = sb + M2A_OFF + (uint32_t)st * 10240u + (uint32_t)r * 80u + (uint32_t)sg2 * 16u;
        cp16(dst, src);
        cp16(dst + 16, src + 8);
    };

    copyA(0, 0);
    CP_COMMIT();
    CP_WAIT0();
    __syncthreads();

    const uint32_t w2H = sb + M2W_OFF;
    const uint32_t w2L = w2H + 16896u;

#pragma unroll 2
    for (int qc = 0; qc < 8; ++qc) {
        const int cst = qc & 1, nst = cst ^ 1;
        const bool more = (qc + 1 < 8);
        if (more) { copyA(qc + 1, nst); CP_COMMIT(); }
        const uint32_t aB = sb + M2A_OFF + (uint32_t)cst * 10240u;
#pragma unroll
        for (int s = 0; s < 2; s++) {
            const uint32_t colB = (uint32_t)(s * 16 + (lane >> 4) * 8) * 2u;
            const uint32_t arow = (uint32_t)(wid * 16 + (lane & 15)) * 80u;
            uint32_t af[4];
            ldm4(af, aB + arow + colB);
            const uint32_t kbyte = (uint32_t)(qc * 32) * 2u + colB;
#pragma unroll
            for (int ng = 0; ng < 2; ng++) {
                const uint32_t brow = (uint32_t)(ng * 16 + (lane & 15)) * 528u;
                uint32_t rh[4], rl[4];
                ldm4(rh, w2H + brow + kbyte);
                ldm4(rl, w2L + brow + kbyte);
                mma16816(acc[ng * 2],     af, rh[0], rh[2]);
                mma16816(acc[ng * 2],     af, rl[0], rl[2]);
                mma16816(acc[ng * 2 + 1], af, rh[1], rh[3]);
                mma16816(acc[ng * 2 + 1], af, rl[1], rl[3]);
            }
        }
        CP_WAIT0();
        __syncthreads();
    }

    // epilogue (fp32 output)
#pragma unroll
    for (int hr = 0; hr < 2; hr++) {
        int row = wid * 16 + (lane >> 2) + hr * 8;
#pragma unroll
        for (int nt = 0; nt < 4; nt++) {
            int col = nt * 8 + (lane & 3) * 2;
            float o0 = acc[nt][hr * 2 + 0] + b2[col];
            float o1 = acc[nt][hr * 2 + 1] + b2[col + 1];
            *(float2*)&out[((size_t)b * NN + n0 + row) * PP + col] = make_float2(o0, o1);
        }
    }
}

// ---------------- launch -----------------------------------------------------------
extern "C" void kernel_launch(void* const* d_in, const int* in_sizes, int n_in,
                              void* d_out, int out_size) {
    (void)in_sizes; (void)n_in; (void)out_size;
    const float* node_feats = (const float*)d_in[0];
    const float* z          = (const float*)d_in[1];
    const int*   children   = (const int*)  d_in[2];
    const float* conv1_w    = (const float*)d_in[3];
    const float* conv1_b    = (const float*)d_in[4];
    const float* conv2_w    = (const float*)d_in[5];
    const float* conv2_b    = (const float*)d_in[6];
    const float* mlp_w1     = (const float*)d_in[7];
    const float* mlp_b1     = (const float*)d_in[8];
    const float* mlp_w2     = (const float*)d_in[9];
    const float* mlp_b2     = (const float*)d_in[10];
    float* out = (float*)d_out;

    static bool attr_done = false;
    if (!attr_done) {
        cudaFuncSetAttribute(k_gemm<0>, cudaFuncAttributeMaxDynamicSharedMemorySize, GEMM_SMEM);
        cudaFuncSetAttribute(k_gemm<1>, cudaFuncAttributeMaxDynamicSharedMemorySize, GEMM_SMEM);
        cudaFuncSetAttribute(k_gemm<2>, cudaFuncAttributeMaxDynamicSharedMemorySize, GEMM_SMEM);
        cudaFuncSetAttribute(k_mlp2,    cudaFuncAttributeMaxDynamicSharedMemorySize, M2_SMEM);
        attr_done = true;
    }

    k_init<<<64, 256>>>();
    k_transpose<<<dim3(NN / 32, CC / 32, BB), dim3(32, 32)>>>(node_feats);
    k_pack<<<256, 256>>>(conv1_w, conv2_w, mlp_w1, mlp_w2);

    k_gemm<0><<<dim3(16, 2, BB), 256, GEMM_SMEM>>>(conv1_b, children, z);
    k_finalize<<<1, 64>>>(0);
    k_gemm<1><<<dim3(16, 2, BB), 256, GEMM_SMEM>>>(conv2_b, children, z);
    k_finalize<<<1, 64>>>(1);
    k_gemm<2><<<dim3(16, 2, BB), 256, GEMM_SMEM>>>(mlp_b1, children, z);

    k_mlp2<<<dim3(16, BB), 256, M2_SMEM>>>(mlp_b2, out);
}

// round 7
// speedup vs baseline: 5.2833x; 1.3396x over previous
#include <cuda_runtime.h>
#include <cuda_fp16.h>
#include <cstdint>
#include <math.h>

#define BB   64
#define CC   64
#define HH   256
#define LL   64
#define PP   32
#define NREAL 2047
#define NN   2048
#define KTOT 1280   // 192 (conv1) + 768 (conv2) + 320 (mlp1)

// ---------------- global scratch ---------------------------------------------
__device__ __align__(16) __half g_xtH [(size_t)BB * NN * CC];
__device__ __align__(16) __half g_buf1[(size_t)BB * NN * HH];
__device__ __align__(16) __half g_buf2[(size_t)BB * NN * HH];
__device__ __align__(16) __half g_wpHi[HH * KTOT];
__device__ __align__(16) __half g_wpLo[HH * KTOT];
__device__ __align__(16) __half g_w2Hi[PP * HH];
__device__ __align__(16) __half g_w2Lo[PP * HH];
__device__ double g_stats[2][BB][2];
__device__ float  g_norm [2][BB][2];

// ---------------- smem layouts -------------------------------------------------
// conv1 (KC=32, B hi/lo):
#define C1A_OFF   0                       // st*10240
#define C1B_OFF   20480                   // (st*2+pl)*10240
#define C1SIDX    61440
#define C1RS      62976
#define C1RSS     63040
#define C1BIAS    63104
#define C1_SMEM   63616
// gemmB (KC=64, B single): A st*18432 @0 ; B st*18432 @36864
#define GBA_OFF   0
#define GBB_OFF   36864
#define GBSIDX    73728
#define GBRS      75264
#define GBRSS     75328
#define GBBIAS    75392
#define GB_SMEM   75904
// mlp2
#define M2A_OFF  0
#define M2W_OFF  20480
#define M2_SMEM  54272

// ---------------- helpers -------------------------------------------------------
__device__ __forceinline__ uint32_t smem_u32(const void* p) {
    uint32_t a;
    asm("{ .reg .u64 t; cvta.to.shared.u64 t, %1; cvt.u32.u64 %0, t; }" : "=r"(a) : "l"(p));
    return a;
}
__device__ __forceinline__ void ldm4(uint32_t* r, uint32_t addr) {
    asm volatile("ldmatrix.sync.aligned.m8n8.x4.shared.b16 {%0,%1,%2,%3}, [%4];"
                 : "=r"(r[0]), "=r"(r[1]), "=r"(r[2]), "=r"(r[3]) : "r"(addr));
}
__device__ __forceinline__ void mma16816(float* c, const uint32_t* a, uint32_t b0, uint32_t b1) {
    asm volatile("mma.sync.aligned.m16n8k16.row.col.f32.f16.f16.f32 "
                 "{%0,%1,%2,%3}, {%4,%5,%6,%7}, {%8,%9}, {%0,%1,%2,%3};"
                 : "+f"(c[0]), "+f"(c[1]), "+f"(c[2]), "+f"(c[3])
                 : "r"(a[0]), "r"(a[1]), "r"(a[2]), "r"(a[3]), "r"(b0), "r"(b1));
}
__device__ __forceinline__ void cp16(uint32_t dst, const void* src) {
    asm volatile("cp.async.cg.shared.global [%0], [%1], 16;" :: "r"(dst), "l"(src));
}
#define CP_COMMIT() asm volatile("cp.async.commit_group;" ::: "memory")
#define CP_WAIT0()  asm volatile("cp.async.wait_group 0;"  ::: "memory")
__device__ __forceinline__ uint32_t pkh(__half a, __half b) {
    return (uint32_t)__half_as_ushort(a) | ((uint32_t)__half_as_ushort(b) << 16);
}
__device__ __forceinline__ uint32_t pkf(float a, float b) {
    return pkh(__float2half(a), __float2half(b));
}

// ---------------- init -----------------------------------------------------------
__global__ void k_init() {
    int t = blockIdx.x * blockDim.x + threadIdx.x;
    if (t < 2 * BB * 2) ((double*)g_stats)[t] = 0.0;
    for (int i = t; i < BB * HH; i += gridDim.x * blockDim.x) {
        int b = i >> 8, h = i & 255;
        g_buf1[(size_t)b * NN * HH + h] = __float2half(0.f);
        g_buf2[(size_t)b * NN * HH + h] = __float2half(0.f);
    }
}

// ---------------- transpose node_feats [B,C,N] -> fp16 [B,N,C] ---------------------
__global__ void k_transpose(const float* __restrict__ x) {
    __shared__ float tile[32][33];
    int b  = blockIdx.z;
    int n0 = blockIdx.x * 32;
    int c0 = blockIdx.y * 32;
    int tx = threadIdx.x, ty = threadIdx.y;
    tile[ty][tx] = x[((size_t)b * CC + c0 + ty) * NN + n0 + tx];
    __syncthreads();
    g_xtH[((size_t)b * NN + n0 + ty) * CC + c0 + tx] = __float2half(tile[tx][ty]);
}

// ---------------- pack weights into fp16 hi/lo -------------------------------------
__global__ void k_pack(const float* __restrict__ w1c, const float* __restrict__ w2c,
                       const float* __restrict__ wm, const float* __restrict__ wm2) {
    int t = blockIdx.x * blockDim.x + threadIdx.x;
    int stride = gridDim.x * blockDim.x;
    for (int e = t; e < HH * KTOT; e += stride) {
        int h = e / KTOT, k = e % KTOT;
        float w;
        if (k < 192)      { int j = k / 64,  c = k % 64;            w = w1c[(h * CC + c) * 3 + j]; }
        else if (k < 960) { int kk = k - 192; int j = kk / 256, c = kk % 256; w = w2c[(h * HH + c) * 3 + j]; }
        else              { int kk = k - 960; w = wm[kk * HH + h]; }
        __half hi = __float2half(w);
        g_wpHi[e] = hi;
        g_wpLo[e] = __float2half(w - __half2float(hi));
    }
    for (int e = t; e < PP * HH; e += stride) {
        int p = e >> 8, k = e & 255;
        float w = wm2[k * PP + p];
        __half hi = __float2half(w);
        g_w2Hi[e] = hi;
        g_w2Lo[e] = __float2half(w - __half2float(hi));
    }
}

// ---------------- conv1: KC=32, B hi/lo (exact weights), cp.async A gather ---------
__global__ void __launch_bounds__(256, 2) k_conv1(const float* __restrict__ bias,
                                                  const int* __restrict__ children) {
    extern __shared__ __align__(16) char smem[];
    constexpr int NCH = 6;

    const int tile = blockIdx.x, hb = blockIdx.y, b = blockIdx.z;
    const int h0   = hb * 128;
    const int nbase = 1 + tile * 128;
    const int tid = threadIdx.x, lane = tid & 31, wid = tid >> 5;
    const int wm = wid & 1, wn = wid >> 1;
    const uint32_t sb = smem_u32(smem);
    int* sidx = (int*)(smem + C1SIDX);

    if (tid < 128) ((float*)(smem + C1BIAS))[tid] = bias[h0 + tid];
    for (int i = tid; i < 384; i += 256) {
        int gn = nbase + i / 3;
        sidx[i] = (gn <= NREAL) ? children[b * 3 * NREAL + (gn - 1) * 3 + (i % 3)] : 0;
    }
    __syncthreads();

    const __half* xtb = g_xtH + (size_t)b * NN * CC;

    float acc[4][4][4];
#pragma unroll
    for (int mt = 0; mt < 4; mt++)
#pragma unroll
        for (int nt = 0; nt < 4; nt++)
#pragma unroll
            for (int q = 0; q < 4; q++) acc[mt][nt][q] = 0.f;

    auto copyB = [&](int qc, int st) {
        const int kofs = qc * 32;
#pragma unroll
        for (int pl = 0; pl < 2; ++pl) {
            const __half* gw = (pl ? g_wpLo : g_wpHi);
            uint32_t dbase = sb + C1B_OFF + (uint32_t)(st * 2 + pl) * 10240u;
#pragma unroll
            for (int u = 0; u < 2; ++u) {
                int seg = tid + u * 256;
                int row = seg >> 2, s4 = seg & 3;
                cp16(dbase + (uint32_t)row * 80u + (uint32_t)s4 * 16u,
                     gw + (size_t)(h0 + row) * KTOT + kofs + s4 * 8);
            }
        }
    };
    auto copyA0 = [&](int qc, int st) {
        const int j = qc >> 1, c0 = (qc & 1) * 32;
        const int r = tid >> 1, sg2 = (tid & 1) * 2;
        int idx = sidx[r * 3 + j];
        const __half* src = xtb + (size_t)idx * CC + c0 + sg2 * 8;
        uint32_t dst = sb + C1A_OFF + (uint32_t)st * 10240u + (uint32_t)r * 80u + (uint32_t)sg2 * 16u;
        cp16(dst, src);
        cp16(dst + 16, src + 8);
    };

    copyB(0, 0);
    copyA0(0, 0);
    CP_COMMIT();
    CP_WAIT0();
    __syncthreads();

#pragma unroll 2
    for (int qc = 0; qc < NCH; ++qc) {
        const int cst = qc & 1, nst = cst ^ 1;
        const bool more = (qc + 1 < NCH);
        if (more) {
            copyB(qc + 1, nst);
            copyA0(qc + 1, nst);
            CP_COMMIT();
        }
        const uint32_t aB = sb + C1A_OFF + (uint32_t)cst * 10240u;
        const uint32_t bH = sb + C1B_OFF + (uint32_t)(cst * 2) * 10240u;
        const uint32_t bL = bH + 10240u;
#pragma unroll
        for (int s = 0; s < 2; s++) {
            const uint32_t colB = (uint32_t)(s * 16 + (lane >> 4) * 8) * 2u;
            uint32_t af[4][4];
            const uint32_t arow = (uint32_t)(wm * 64 + (lane & 15)) * 80u;
#pragma unroll
            for (int mt = 0; mt < 4; mt++)
                ldm4(af[mt], aB + arow + (uint32_t)mt * (16 * 80) + colB);
#pragma unroll
            for (int pl = 0; pl < 2; pl++) {
                const uint32_t bb = pl ? bL : bH;
#pragma unroll
                for (int ng = 0; ng < 2; ng++) {
                    uint32_t rb[4];
                    const uint32_t brow = (uint32_t)(wn * 32 + ng * 16 + (lane & 15)) * 80u;
                    ldm4(rb, bb + brow + colB);
#pragma unroll
                    for (int mt = 0; mt < 4; mt++) {
                        mma16816(acc[mt][ng * 2 + 0], af[mt], rb[0], rb[2]);
                        mma16816(acc[mt][ng * 2 + 1], af[mt], rb[1], rb[3]);
                    }
                }
            }
        }
        CP_WAIT0();
        __syncthreads();
    }

    // epilogue: bias, fp16 store, stats
    const float* sBias = (const float*)(smem + C1BIAS);
    float s = 0.f, ss = 0.f;
#pragma unroll
    for (int mt = 0; mt < 4; mt++) {
#pragma unroll
        for (int hr = 0; hr < 2; hr++) {
            int rrow = wm * 64 + mt * 16 + (lane >> 2) + hr * 8;
            int gn   = nbase + rrow;
            if (gn <= NREAL) {
                __half* drow = g_buf1 + ((size_t)b * NN + gn) * HH + h0;
#pragma unroll
                for (int nt = 0; nt < 4; nt++) {
                    int col = wn * 32 + nt * 8 + (lane & 3) * 2;
                    float o0 = acc[mt][nt][hr * 2 + 0] + sBias[col];
                    float o1 = acc[mt][nt][hr * 2 + 1] + sBias[col + 1];
                    *(uint32_t*)&drow[col] = pkf(o0, o1);
                    s += o0 + o1; ss += o0 * o0 + o1 * o1;
                }
            }
        }
    }
#pragma unroll
    for (int off = 16; off > 0; off >>= 1) {
        s  += __shfl_down_sync(0xffffffffu, s,  off);
        ss += __shfl_down_sync(0xffffffffu, ss, off);
    }
    float* rs  = (float*)(smem + C1RS);
    float* rss = (float*)(smem + C1RSS);
    if (lane == 0) { rs[wid] = s; rss[wid] = ss; }
    __syncthreads();
    if (tid == 0) {
        float S = 0.f, SS = 0.f;
#pragma unroll
        for (int w = 0; w < 8; w++) { S += rs[w]; SS += rss[w]; }
        atomicAdd(&g_stats[0][b][0], (double)S);
        atomicAdd(&g_stats[0][b][1], (double)SS);
    }
}

// ---------------- gemmB: stages 1,2 — KC=64, single-plane B ------------------------
// STAGE 1: conv2 src=g_buf1 (K=768, gather+norm0+relu)  -> g_buf2 + stats1
// STAGE 2: mlp1  src=g_buf2 (K=320: 256 norm1+relu, 64 z) -> relu -> g_buf1
template <int STAGE>
__global__ void __launch_bounds__(256, 2) k_gemmB(const float* __restrict__ bias,
                                                  const int* __restrict__ children,
                                                  const float* __restrict__ zin) {
    extern __shared__ __align__(16) char smem[];
    constexpr int NCH   = (STAGE == 1) ? 12 : 5;
    constexpr int KBASE = (STAGE == 1) ? 192 : 960;

    const int tile = blockIdx.x, hb = blockIdx.y, b = blockIdx.z;
    const int h0   = hb * 128;
    const int nbase = (STAGE == 2) ? tile * 128 : 1 + tile * 128;
    const int tid = threadIdx.x, lane = tid & 31, wid = tid >> 5;
    const int wm = wid & 1, wn = wid >> 1;
    const uint32_t sb = smem_u32(smem);
    int* sidx = (int*)(smem + GBSIDX);

    const float mean = g_norm[STAGE - 1][b][0];
    const float istd = g_norm[STAGE - 1][b][1];

    if (tid < 128) ((float*)(smem + GBBIAS))[tid] = bias[h0 + tid];
    if (STAGE == 1) {
        for (int i = tid; i < 384; i += 256) {
            int gn = nbase + i / 3;
            sidx[i] = (gn <= NREAL) ? children[b * 3 * NREAL + (gn - 1) * 3 + (i % 3)] : 0;
        }
    }
    __syncthreads();

    const __half* srcb = ((STAGE == 1) ? g_buf1 : g_buf2) + (size_t)b * NN * HH;
    const int m = tid >> 1, half_ = tid & 1;

    float acc[4][4][4];
#pragma unroll
    for (int mt = 0; mt < 4; mt++)
#pragma unroll
        for (int nt = 0; nt < 4; nt++)
#pragma unroll
            for (int q = 0; q < 4; q++) acc[mt][nt][q] = 0.f;

    auto copyB = [&](int qc, int st) {
        const int kofs = KBASE + qc * 64;
        const int row = tid >> 1, sec = tid & 1;
        const __half* src = g_wpHi + (size_t)(h0 + row) * KTOT + kofs + sec * 32;
        uint32_t dst = sb + GBB_OFF + (uint32_t)st * 18432u + (uint32_t)row * 144u + (uint32_t)sec * 64u;
        cp16(dst,      src);
        cp16(dst + 16, src + 8);
        cp16(dst + 32, src + 16);
        cp16(dst + 48, src + 24);
    };
    // gather + norm + relu → 16 packed u32 (32 halfs)
    auto loadA = [&](int qc, uint32_t* v) {
        if (STAGE == 2 && qc == 4) {
            const float4* zp = (const float4*)(zin + b * LL + half_ * 32);
#pragma unroll
            for (int f = 0; f < 8; f++) {
                float4 t = zp[f];
                v[2 * f]     = pkf(t.x, t.y);
                v[2 * f + 1] = pkf(t.z, t.w);
            }
        } else {
            int row, c0;
            if (STAGE == 1) { int j = qc >> 2; c0 = (qc & 3) * 64; row = sidx[m * 3 + j]; }
            else            { c0 = qc * 64; row = nbase + m; }
            const uint4* p = (const uint4*)(srcb + (size_t)row * HH + c0 + half_ * 32);
#pragma unroll
            for (int u = 0; u < 4; u++) {
                uint4 q4 = p[u];
                const uint32_t* w = (const uint32_t*)&q4;
#pragma unroll
                for (int e = 0; e < 4; e++) {
                    float2 fv = __half22float2(*(const __half2*)&w[e]);
                    fv.x = fmaxf((fv.x - mean) * istd, 0.f);
                    fv.y = fmaxf((fv.y - mean) * istd, 0.f);
                    v[u * 4 + e] = pkf(fv.x, fv.y);
                }
            }
        }
    };
    auto stsA = [&](const uint32_t* v, int st) {
        char* a = smem + GBA_OFF + st * 18432 + m * 144 + half_ * 64;
        *(uint4*)(a)      = make_uint4(v[0],  v[1],  v[2],  v[3]);
        *(uint4*)(a + 16) = make_uint4(v[4],  v[5],  v[6],  v[7]);
        *(uint4*)(a + 32) = make_uint4(v[8],  v[9],  v[10], v[11]);
        *(uint4*)(a + 48) = make_uint4(v[12], v[13], v[14], v[15]);
    };

    uint32_t areg[16];
    copyB(0, 0);
    CP_COMMIT();
    loadA(0, areg);
    stsA(areg, 0);
    CP_WAIT0();
    __syncthreads();

#pragma unroll 2
    for (int qc = 0; qc < NCH; ++qc) {
        const int cst = qc & 1, nst = cst ^ 1;
        const bool more = (qc + 1 < NCH);
        if (more) {
            copyB(qc + 1, nst);
            CP_COMMIT();
            loadA(qc + 1, areg);
        }
        const uint32_t aB = sb + GBA_OFF + (uint32_t)cst * 18432u;
        const uint32_t bB = sb + GBB_OFF + (uint32_t)cst * 18432u;
#pragma unroll
        for (int s = 0; s < 4; s++) {
            const uint32_t colB = (uint32_t)(s * 16 + (lane >> 4) * 8) * 2u;
            uint32_t af[4][4];
            const uint32_t arow = (uint32_t)(wm * 64 + (lane & 15)) * 144u;
#pragma unroll
            for (int mt = 0; mt < 4; mt++)
                ldm4(af[mt], aB + arow + (uint32_t)mt * (16 * 144) + colB);
#pragma unroll
            for (int ng = 0; ng < 2; ng++) {
                uint32_t rb[4];
                const uint32_t brow = (uint32_t)(wn * 32 + ng * 16 + (lane & 15)) * 144u;
                ldm4(rb, bB + brow + colB);
#pragma unroll
                for (int mt = 0; mt < 4; mt++) {
                    mma16816(acc[mt][ng * 2 + 0], af[mt], rb[0], rb[2]);
                    mma16816(acc[mt][ng * 2 + 1], af[mt], rb[1], rb[3]);
                }
            }
        }
        if (more) stsA(areg, nst);
        CP_WAIT0();
        __syncthreads();
    }

    // epilogue
    __half* dst = (STAGE == 1) ? g_buf2 : g_buf1;
    const float* sBias = (const float*)(smem + GBBIAS);
    float s = 0.f, ss = 0.f;
#pragma unroll
    for (int mt = 0; mt < 4; mt++) {
#pragma unroll
        for (int hr = 0; hr < 2; hr++) {
            int rrow = wm * 64 + mt * 16 + (lane >> 2) + hr * 8;
            int gn   = nbase + rrow;
            bool valid = (STAGE == 2) || (gn <= NREAL);
            if (valid) {
                __half* drow = dst + ((size_t)b * NN + gn) * HH + h0;
#pragma unroll
                for (int nt = 0; nt < 4; nt++) {
                    int col = wn * 32 + nt * 8 + (lane & 3) * 2;
                    float o0 = acc[mt][nt][hr * 2 + 0] + sBias[col];
                    float o1 = acc[mt][nt][hr * 2 + 1] + sBias[col + 1];
                    if (STAGE == 2) { o0 = fmaxf(o0, 0.f); o1 = fmaxf(o1, 0.f); }
                    *(uint32_t*)&drow[col] = pkf(o0, o1);
                    if (STAGE == 1) { s += o0 + o1; ss += o0 * o0 + o1 * o1; }
                }
            }
        }
    }
    if (STAGE == 1) {
#pragma unroll
        for (int off = 16; off > 0; off >>= 1) {
            s  += __shfl_down_sync(0xffffffffu, s,  off);
            ss += __shfl_down_sync(0xffffffffu, ss, off);
        }
        float* rs  = (float*)(smem + GBRS);
        float* rss = (float*)(smem + GBRSS);
        if (lane == 0) { rs[wid] = s; rss[wid] = ss; }
        __syncthreads();
        if (tid == 0) {
            float S = 0.f, SS = 0.f;
#pragma unroll
            for (int w = 0; w < 8; w++) { S += rs[w]; SS += rss[w]; }
            atomicAdd(&g_stats[1][b][0], (double)S);
            atomicAdd(&g_stats[1][b][1], (double)SS);
        }
    }
}

// ---------------- finalize norm stats ------------------------------------------
__global__ void k_finalize(int stage) {
    int b = threadIdx.x;
    if (b < BB) {
        double s  = g_stats[stage][b][0];
        double ss = g_stats[stage][b][1];
        const double cnt = (double)HH * (double)NN;
        double mean = s / cnt;
        double var  = (ss - s * s / cnt) / (cnt - 1.0);
        if (var < 0.0) var = 0.0;
        double sd = sqrt(var) + 1e-5;
        g_norm[stage][b][0] = (float)mean;
        g_norm[stage][b][1] = (float)(1.0 / sd);
    }
}

// ---------------- MLP layer 2 via mma (fp16 A via cp.async, B hi/lo) --------------
__global__ void __launch_bounds__(256, 2) k_mlp2(const float* __restrict__ b2,
                                                 float* __restrict__ out) {
    extern __shared__ __align__(16) char smem[];
    const int b   = blockIdx.y;
    const int n0  = blockIdx.x * 128;
    const int tid = threadIdx.x, lane = tid & 31, wid = tid >> 5;
    const uint32_t sb = smem_u32(smem);

#pragma unroll
    for (int pl = 0; pl < 2; ++pl) {
        const __half* gw = (pl ? g_w2Lo : g_w2Hi);
        char* dbase = smem + M2W_OFF + pl * 16896;
#pragma unroll
        for (int u = 0; u < 4; ++u) {
            int seg = tid + u * 256;
            int row = seg >> 5, s16 = seg & 31;
            *(uint4*)(dbase + row * 528 + s16 * 16) = *(const uint4*)(gw + row * 256 + s16 * 8);
        }
    }

    const __half* srcb = g_buf1 + ((size_t)b * NN + n0) * HH;
    const int r = tid >> 1, sg2 = (tid & 1) * 2;

    float acc[4][4];
#pragma unroll
    for (int nt = 0; nt < 4; nt++)
#pragma unroll
        for (int q = 0; q < 4; q++) acc[nt][q] = 0.f;

    auto copyA = [&](int qc, int st) {
        const __half* src = srcb + (size_t)r * HH + qc * 32 + sg2 * 8;
        uint32_t dst = sb + M2A_OFF + (uint32_t)st * 10240u + (uint32_t)r * 80u + (uint32_t)sg2 * 16u;
        cp16(dst, src);
        cp16(dst + 16, src + 8);
    };

    copyA(0, 0);
    CP_COMMIT();
    CP_WAIT0();
    __syncthreads();

    const uint32_t w2H = sb + M2W_OFF;
    const uint32_t w2L = w2H + 16896u;

#pragma unroll 2
    for (int qc = 0; qc < 8; ++qc) {
        const int cst = qc & 1, nst = cst ^ 1;
        const bool more = (qc + 1 < 8);
        if (more) { copyA(qc + 1, nst); CP_COMMIT(); }
        const uint32_t aB = sb + M2A_OFF + (uint32_t)cst * 10240u;
#pragma unroll
        for (int s = 0; s < 2; s++) {
            const uint32_t colB = (uint32_t)(s * 16 + (lane >> 4) * 8) * 2u;
            const uint32_t arow = (uint32_t)(wid * 16 + (lane & 15)) * 80u;
            uint32_t af[4];
            ldm4(af, aB + arow + colB);
            const uint32_t kbyte = (uint32_t)(qc * 32) * 2u + colB;
#pragma unroll
            for (int ng = 0; ng < 2; ng++) {
                const uint32_t brow = (uint32_t)(ng * 16 + (lane & 15)) * 528u;
                uint32_t rh[4], rl[4];
                ldm4(rh, w2H + brow + kbyte);
                ldm4(rl, w2L + brow + kbyte);
                mma16816(acc[ng * 2],     af, rh[0], rh[2]);
                mma16816(acc[ng * 2],     af, rl[0], rl[2]);
                mma16816(acc[ng * 2 + 1], af, rh[1], rh[3]);
                mma16816(acc[ng * 2 + 1], af, rl[1], rl[3]);
            }
        }
        CP_WAIT0();
        __syncthreads();
    }

#pragma unroll
    for (int hr = 0; hr < 2; hr++) {
        int row = wid * 16 + (lane >> 2) + hr * 8;
#pragma unroll
        for (int nt = 0; nt < 4; nt++) {
            int col = nt * 8 + (lane & 3) * 2;
            float o0 = acc[nt][hr * 2 + 0] + b2[col];
            float o1 = acc[nt][hr * 2 + 1] + b2[col + 1];
            *(float2*)&out[((size_t)b * NN + n0 + row) * PP + col] = make_float2(o0, o1);
        }
    }
}

// ---------------- launch -----------------------------------------------------------
extern "C" void kernel_launch(void* const* d_in, const int* in_sizes, int n_in,
                              void* d_out, int out_size) {
    (void)in_sizes; (void)n_in; (void)out_size;
    const float* node_feats = (const float*)d_in[0];
    const float* z          = (const float*)d_in[1];
    const int*   children   = (const int*)  d_in[2];
    const float* conv1_w    = (const float*)d_in[3];
    const float* conv1_b    = (const float*)d_in[4];
    const float* conv2_w    = (const float*)d_in[5];
    const float* conv2_b    = (const float*)d_in[6];
    const float* mlp_w1     = (const float*)d_in[7];
    const float* mlp_b1     = (const float*)d_in[8];
    const float* mlp_w2     = (const float*)d_in[9];
    const float* mlp_b2     = (const float*)d_in[10];
    float* out = (float*)d_out;

    static bool attr_done = false;
    if (!attr_done) {
        cudaFuncSetAttribute(k_conv1,    cudaFuncAttributeMaxDynamicSharedMemorySize, C1_SMEM);
        cudaFuncSetAttribute(k_gemmB<1>, cudaFuncAttributeMaxDynamicSharedMemorySize, GB_SMEM);
        cudaFuncSetAttribute(k_gemmB<2>, cudaFuncAttributeMaxDynamicSharedMemorySize, GB_SMEM);
        cudaFuncSetAttribute(k_mlp2,     cudaFuncAttributeMaxDynamicSharedMemorySize, M2_SMEM);
        attr_done = true;
    }

    k_init<<<64, 256>>>();
    k_transpose<<<dim3(NN / 32, CC / 32, BB), dim3(32, 32)>>>(node_feats);
    k_pack<<<256, 256>>>(conv1_w, conv2_w, mlp_w1, mlp_w2);

    k_conv1<<<dim3(16, 2, BB), 256, C1_SMEM>>>(conv1_b, children);
    k_finalize<<<1, 64>>>(0);
    k_gemmB<1><<<dim3(16, 2, BB), 256, GB_SMEM>>>(conv2_b, children, z);
    k_finalize<<<1, 64>>>(1);
    k_gemmB<2><<<dim3(16, 2, BB), 256, GB_SMEM>>>(mlp_b1, children, z);

    k_mlp2<<<dim3(16, BB), 256, M2_SMEM>>>(mlp_b2, out);
}

// round 8
// speedup vs baseline: 5.4911x; 1.0393x over previous
#include <cuda_runtime.h>
#include <cuda_fp16.h>
#include <cstdint>
#include <math.h>

#define BB   64
#define CC   64
#define HH   256
#define LL   64
#define PP   32
#define NREAL 2047
#define NN   2048
#define KTOT 1280   // 192 (conv1) + 768 (conv2) + 320 (mlp1)

// ---------------- global scratch ---------------------------------------------
__device__ __align__(16) __half g_xtH [(size_t)BB * NN * CC];
__device__ __align__(16) __half g_buf1[(size_t)BB * NN * HH];
__device__ __align__(16) __half g_buf2[(size_t)BB * NN * HH];
__device__ __align__(16) __half g_wpHi[HH * KTOT];
__device__ __align__(16) __half g_w2Hi[PP * HH];
__device__ __align__(16) __half g_w2Lo[PP * HH];
__device__ double g_stats[2][BB][2];
__device__ float  g_norm [2][BB][2];

// ---------------- smem layouts -------------------------------------------------
// unified gemm (KC=64, single-plane B): A st*18432 @0 ; B st*18432 @36864
#define GBA_OFF   0
#define GBB_OFF   36864
#define GBSIDX    73728
#define GBRS      75264
#define GBRSS     75328
#define GBBIAS    75392
#define GB_SMEM   75904
// mlp2
#define M2A_OFF  0
#define M2W_OFF  20480
#define M2_SMEM  54272

// ---------------- helpers -------------------------------------------------------
__device__ __forceinline__ uint32_t smem_u32(const void* p) {
    uint32_t a;
    asm("{ .reg .u64 t; cvta.to.shared.u64 t, %1; cvt.u32.u64 %0, t; }" : "=r"(a) : "l"(p));
    return a;
}
__device__ __forceinline__ void ldm4(uint32_t* r, uint32_t addr) {
    asm volatile("ldmatrix.sync.aligned.m8n8.x4.shared.b16 {%0,%1,%2,%3}, [%4];"
                 : "=r"(r[0]), "=r"(r[1]), "=r"(r[2]), "=r"(r[3]) : "r"(addr));
}
__device__ __forceinline__ void mma16816(float* c, const uint32_t* a, uint32_t b0, uint32_t b1) {
    asm volatile("mma.sync.aligned.m16n8k16.row.col.f32.f16.f16.f32 "
                 "{%0,%1,%2,%3}, {%4,%5,%6,%7}, {%8,%9}, {%0,%1,%2,%3};"
                 : "+f"(c[0]), "+f"(c[1]), "+f"(c[2]), "+f"(c[3])
                 : "r"(a[0]), "r"(a[1]), "r"(a[2]), "r"(a[3]), "r"(b0), "r"(b1));
}
__device__ __forceinline__ void cp16(uint32_t dst, const void* src) {
    asm volatile("cp.async.cg.shared.global [%0], [%1], 16;" :: "r"(dst), "l"(src));
}
#define CP_COMMIT() asm volatile("cp.async.commit_group;" ::: "memory")
#define CP_WAIT0()  asm volatile("cp.async.wait_group 0;"  ::: "memory")
__device__ __forceinline__ uint32_t pkh(__half a, __half b) {
    return (uint32_t)__half_as_ushort(a) | ((uint32_t)__half_as_ushort(b) << 16);
}
__device__ __forceinline__ uint32_t pkf(float a, float b) {
    return pkh(__float2half(a), __float2half(b));
}

// ---------------- init -----------------------------------------------------------
__global__ void k_init() {
    int t = blockIdx.x * blockDim.x + threadIdx.x;
    if (t < 2 * BB * 2) ((double*)g_stats)[t] = 0.0;
    for (int i = t; i < BB * HH; i += gridDim.x * blockDim.x) {
        int b = i >> 8, h = i & 255;
        g_buf1[(size_t)b * NN * HH + h] = __float2half(0.f);
        g_buf2[(size_t)b * NN * HH + h] = __float2half(0.f);
    }
}

// ---------------- transpose node_feats [B,C,N] -> fp16 [B,N,C] ---------------------
__global__ void k_transpose(const float* __restrict__ x) {
    __shared__ float tile[32][33];
    int b  = blockIdx.z;
    int n0 = blockIdx.x * 32;
    int c0 = blockIdx.y * 32;
    int tx = threadIdx.x, ty = threadIdx.y;
    tile[ty][tx] = x[((size_t)b * CC + c0 + ty) * NN + n0 + tx];
    __syncthreads();
    g_xtH[((size_t)b * NN + n0 + ty) * CC + c0 + tx] = __float2half(tile[tx][ty]);
}

// ---------------- pack weights into fp16 (hi only for big W; hi/lo for W2) ---------
__global__ void k_pack(const float* __restrict__ w1c, const float* __restrict__ w2c,
                       const float* __restrict__ wm, const float* __restrict__ wm2) {
    int t = blockIdx.x * blockDim.x + threadIdx.x;
    int stride = gridDim.x * blockDim.x;
    for (int e = t; e < HH * KTOT; e += stride) {
        int h = e / KTOT, k = e % KTOT;
        float w;
        if (k < 192)      { int j = k / 64,  c = k % 64;            w = w1c[(h * CC + c) * 3 + j]; }
        else if (k < 960) { int kk = k - 192; int j = kk / 256, c = kk % 256; w = w2c[(h * HH + c) * 3 + j]; }
        else              { int kk = k - 960; w = wm[kk * HH + h]; }
        g_wpHi[e] = __float2half(w);
    }
    for (int e = t; e < PP * HH; e += stride) {
        int p = e >> 8, k = e & 255;
        float w = wm2[k * PP + p];
        __half hi = __float2half(w);
        g_w2Hi[e] = hi;
        g_w2Lo[e] = __float2half(w - __half2float(hi));
    }
}

// ---------------- unified gather + mma.sync GEMM (KC=64, single-plane B) -----------
// STAGE 0: conv1 src=g_xtH (K=192, cp.async gather)        -> g_buf1 + stats0
// STAGE 1: conv2 src=g_buf1 (K=768, gather+norm0+relu)     -> g_buf2 + stats1
// STAGE 2: mlp1  src=g_buf2 (K=320: 256 norm1+relu, 64 z)  -> relu -> g_buf1
template <int STAGE>
__global__ void __launch_bounds__(256, 2) k_gemm(const float* __restrict__ bias,
                                                 const int* __restrict__ children,
                                                 const float* __restrict__ zin) {
    extern __shared__ __align__(16) char smem[];
    constexpr int NCH   = (STAGE == 0) ? 3 : (STAGE == 1) ? 12 : 5;
    constexpr int KBASE = (STAGE == 0) ? 0 : (STAGE == 1) ? 192 : 960;

    const int tile = blockIdx.x, hb = blockIdx.y, b = blockIdx.z;
    const int h0   = hb * 128;
    const int nbase = (STAGE == 2) ? tile * 128 : 1 + tile * 128;
    const int tid = threadIdx.x, lane = tid & 31, wid = tid >> 5;
    const int wm = wid & 1, wn = wid >> 1;
    const uint32_t sb = smem_u32(smem);
    int* sidx = (int*)(smem + GBSIDX);

    float mean = 0.f, istd = 1.f;
    if (STAGE >= 1) { mean = g_norm[STAGE - 1][b][0]; istd = g_norm[STAGE - 1][b][1]; }

    if (tid < 128) ((float*)(smem + GBBIAS))[tid] = bias[h0 + tid];
    if (STAGE < 2) {
        for (int i = tid; i < 384; i += 256) {
            int gn = nbase + i / 3;
            sidx[i] = (gn <= NREAL) ? children[b * 3 * NREAL + (gn - 1) * 3 + (i % 3)] : 0;
        }
    }
    __syncthreads();

    const __half* srcb = ((STAGE == 1) ? g_buf1 : g_buf2) + (size_t)b * NN * HH;
    const __half* xtb  = g_xtH + (size_t)b * NN * CC;
    const int m = tid >> 1, half_ = tid & 1;

    float acc[4][4][4];
#pragma unroll
    for (int mt = 0; mt < 4; mt++)
#pragma unroll
        for (int nt = 0; nt < 4; nt++)
#pragma unroll
            for (int q = 0; q < 4; q++) acc[mt][nt][q] = 0.f;

    auto copyB = [&](int qc, int st) {
        const int kofs = KBASE + qc * 64;
        const int row = tid >> 1, sec = tid & 1;
        const __half* src = g_wpHi + (size_t)(h0 + row) * KTOT + kofs + sec * 32;
        uint32_t dst = sb + GBB_OFF + (uint32_t)st * 18432u + (uint32_t)row * 144u + (uint32_t)sec * 64u;
        cp16(dst,      src);
        cp16(dst + 16, src + 8);
        cp16(dst + 32, src + 16);
        cp16(dst + 48, src + 24);
    };
    // STAGE 0: pure cp.async A gather (fp16 source, CIN=64 = one chunk per j)
    auto copyA0 = [&](int qc, int st) {
        int idx = sidx[m * 3 + qc];
        const __half* src = xtb + (size_t)idx * CC + half_ * 32;
        uint32_t dst = sb + GBA_OFF + (uint32_t)st * 18432u + (uint32_t)m * 144u + (uint32_t)half_ * 64u;
        cp16(dst,      src);
        cp16(dst + 16, src + 8);
        cp16(dst + 32, src + 16);
        cp16(dst + 48, src + 24);
    };
    // STAGES 1,2: gather + norm + relu -> 16 packed u32 (32 halfs)
    auto loadA = [&](int qc, uint32_t* v) {
        if (STAGE == 2 && qc == 4) {
            const float4* zp = (const float4*)(zin + b * LL + half_ * 32);
#pragma unroll
            for (int f = 0; f < 8; f++) {
                float4 t = zp[f];
                v[2 * f]     = pkf(t.x, t.y);
                v[2 * f + 1] = pkf(t.z, t.w);
            }
        } else {
            int row, c0;
            if (STAGE == 1) { int j = qc >> 2; c0 = (qc & 3) * 64; row = sidx[m * 3 + j]; }
            else            { c0 = qc * 64; row = nbase + m; }
            const uint4* p = (const uint4*)(srcb + (size_t)row * HH + c0 + half_ * 32);
#pragma unroll
            for (int u = 0; u < 4; u++) {
                uint4 q4 = p[u];
                const uint32_t* w = (const uint32_t*)&q4;
#pragma unroll
                for (int e = 0; e < 4; e++) {
                    float2 fv = __half22float2(*(const __half2*)&w[e]);
                    fv.x = fmaxf((fv.x - mean) * istd, 0.f);
                    fv.y = fmaxf((fv.y - mean) * istd, 0.f);
                    v[u * 4 + e] = pkf(fv.x, fv.y);
                }
            }
        }
    };
    auto stsA = [&](const uint32_t* v, int st) {
        char* a = smem + GBA_OFF + st * 18432 + m * 144 + half_ * 64;
        *(uint4*)(a)      = make_uint4(v[0],  v[1],  v[2],  v[3]);
        *(uint4*)(a + 16) = make_uint4(v[4],  v[5],  v[6],  v[7]);
        *(uint4*)(a + 32) = make_uint4(v[8],  v[9],  v[10], v[11]);
        *(uint4*)(a + 48) = make_uint4(v[12], v[13], v[14], v[15]);
    };

    // ---- prologue ----
    uint32_t areg[16];
    copyB(0, 0);
    if (STAGE == 0) {
        copyA0(0, 0);
        CP_COMMIT();
    } else {
        CP_COMMIT();
        loadA(0, areg);
        stsA(areg, 0);
    }
    CP_WAIT0();
    __syncthreads();

    // ---- main loop ----
#pragma unroll 2
    for (int qc = 0; qc < NCH; ++qc) {
        const int cst = qc & 1, nst = cst ^ 1;
        const bool more = (qc + 1 < NCH);
        if (more) {
            copyB(qc + 1, nst);
            if (STAGE == 0) copyA0(qc + 1, nst);
            CP_COMMIT();
            if (STAGE != 0) loadA(qc + 1, areg);
        }
        const uint32_t aB = sb + GBA_OFF + (uint32_t)cst * 18432u;
        const uint32_t bB = sb + GBB_OFF + (uint32_t)cst * 18432u;
#pragma unroll
        for (int s = 0; s < 4; s++) {
            const uint32_t colB = (uint32_t)(s * 16 + (lane >> 4) * 8) * 2u;
            uint32_t af[4][4];
            const uint32_t arow = (uint32_t)(wm * 64 + (lane & 15)) * 144u;
#pragma unroll
            for (int mt = 0; mt < 4; mt++)
                ldm4(af[mt], aB + arow + (uint32_t)mt * (16 * 144) + colB);
#pragma unroll
            for (int ng = 0; ng < 2; ng++) {
                uint32_t rb[4];
                const uint32_t brow = (uint32_t)(wn * 32 + ng * 16 + (lane & 15)) * 144u;
                ldm4(rb, bB + brow + colB);
#pragma unroll
                for (int mt = 0; mt < 4; mt++) {
                    mma16816(acc[mt][ng * 2 + 0], af[mt], rb[0], rb[2]);
                    mma16816(acc[mt][ng * 2 + 1], af[mt], rb[1], rb[3]);
                }
            }
        }
        if (more && STAGE != 0) stsA(areg, nst);
        CP_WAIT0();
        __syncthreads();
    }

    // ---- epilogue: bias (+relu), fp16 store, stats ----
    __half* dst = (STAGE == 1) ? g_buf2 : g_buf1;
    const float* sBias = (const float*)(smem + GBBIAS);
    float s = 0.f, ss = 0.f;
#pragma unroll
    for (int mt = 0; mt < 4; mt++) {
#pragma unroll
        for (int hr = 0; hr < 2; hr++) {
            int rrow = wm * 64 + mt * 16 + (lane >> 2) + hr * 8;
            int gn   = nbase + rrow;
            bool valid = (STAGE == 2) || (gn <= NREAL);
            if (valid) {
                __half* drow = dst + ((size_t)b * NN + gn) * HH + h0;
#pragma unroll
                for (int nt = 0; nt < 4; nt++) {
                    int col = wn * 32 + nt * 8 + (lane & 3) * 2;
                    float o0 = acc[mt][nt][hr * 2 + 0] + sBias[col];
                    float o1 = acc[mt][nt][hr * 2 + 1] + sBias[col + 1];
                    if (STAGE == 2) { o0 = fmaxf(o0, 0.f); o1 = fmaxf(o1, 0.f); }
                    *(uint32_t*)&drow[col] = pkf(o0, o1);
                    if (STAGE != 2) { s += o0 + o1; ss += o0 * o0 + o1 * o1; }
                }
            }
        }
    }
    if (STAGE != 2) {
#pragma unroll
        for (int off = 16; off > 0; off >>= 1) {
            s  += __shfl_down_sync(0xffffffffu, s,  off);
            ss += __shfl_down_sync(0xffffffffu, ss, off);
        }
        float* rs  = (float*)(smem + GBRS);
        float* rss = (float*)(smem + GBRSS);
        if (lane == 0) { rs[wid] = s; rss[wid] = ss; }
        __syncthreads();
        if (tid == 0) {
            float S = 0.f, SS = 0.f;
#pragma unroll
            for (int w = 0; w < 8; w++) { S += rs[w]; SS += rss[w]; }
            atomicAdd(&g_stats[STAGE][b][0], (double)S);
            atomicAdd(&g_stats[STAGE][b][1], (double)SS);
        }
    }
}

// ---------------- finalize norm stats ------------------------------------------
__global__ void k_finalize(int stage) {
    int b = threadIdx.x;
    if (b < BB) {
        double s  = g_stats[stage][b][0];
        double ss = g_stats[stage][b][1];
        const double cnt = (double)HH * (double)NN;
        double mean = s / cnt;
        double var  = (ss - s * s / cnt) / (cnt - 1.0);
        if (var < 0.0) var = 0.0;
        double sd = sqrt(var) + 1e-5;
        g_norm[stage][b][0] = (float)mean;
        g_norm[stage][b][1] = (float)(1.0 / sd);
    }
}

// ---------------- MLP layer 2 via mma (fp16 A via cp.async, B hi/lo) --------------
__global__ void __launch_bounds__(256, 2) k_mlp2(const float* __restrict__ b2,
                                                 float* __restrict__ out) {
    extern __shared__ __align__(16) char smem[];
    const int b   = blockIdx.y;
    const int n0  = blockIdx.x * 128;
    const int tid = threadIdx.x, lane = tid & 31, wid = tid >> 5;
    const uint32_t sb = smem_u32(smem);

#pragma unroll
    for (int pl = 0; pl < 2; ++pl) {
        const __half* gw = (pl ? g_w2Lo : g_w2Hi);
        char* dbase = smem + M2W_OFF + pl * 16896;
#pragma unroll
        for (int u = 0; u < 4; ++u) {
            int seg = tid + u * 256;
            int row = seg >> 5, s16 = seg & 31;
            *(uint4*)(dbase + row * 528 + s16 * 16) = *(const uint4*)(gw + row * 256 + s16 * 8);
        }
    }

    const __half* srcb = g_buf1 + ((size_t)b * NN + n0) * HH;
    const int r = tid >> 1, sg2 = (tid & 1) * 2;

    float acc[4][4];
#pragma unroll
    for (int nt = 0; nt < 4; nt++)
#pragma unroll
        for (int q = 0; q < 4; q++) acc[nt][q] = 0.f;

    auto copyA = [&](int qc, int st) {
        const __half* src = srcb + (size_t)r * HH + qc * 32 + sg2 * 8;
        uint32_t dst = sb + M2A_OFF + (uint32_t)st * 10240u + (uint32_t)r * 80u + (uint32_t)sg2 * 16u;
        cp16(dst, src);
        cp16(dst + 16, src + 8);
    };

    copyA(0, 0);
    CP_COMMIT();
    CP_WAIT0();
    __syncthreads();

    const uint32_t w2H = sb + M2W_OFF;
    const uint32_t w2L = w2H + 16896u;

#pragma unroll 2
    for (int qc = 0; qc < 8; ++qc) {
        const int cst = qc & 1, nst = cst ^ 1;
        const bool more = (qc + 1 < 8);
        if (more) { copyA(qc + 1, nst); CP_COMMIT(); }
        const uint32_t aB = sb + M2A_OFF + (uint32_t)cst * 10240u;
#pragma unroll
        for (int s = 0; s < 2; s++) {
            const uint32_t colB = (uint32_t)(s * 16 + (lane >> 4) * 8) * 2u;
            const uint32_t arow = (uint32_t)(wid * 16 + (lane & 15)) * 80u;
            uint32_t af[4];
            ldm4(af, aB + arow + colB);
            const uint32_t kbyte = (uint32_t)(qc * 32) * 2u + colB;
#pragma unroll
            for (int ng = 0; ng < 2; ng++) {
                const uint32_t brow = (uint32_t)(ng * 16 + (lane & 15)) * 528u;
                uint32_t rh[4], rl[4];
                ldm4(rh, w2H + brow + kbyte);
                ldm4(rl, w2L + brow + kbyte);
                mma16816(acc[ng * 2],     af, rh[0], rh[2]);
                mma16816(acc[ng * 2],     af, rl[0], rl[2]);
                mma16816(acc[ng * 2 + 1], af, rh[1], rh[3]);
                mma16816(acc[ng * 2 + 1], af, rl[1], rl[3]);
            }
        }
        CP_WAIT0();
        __syncthreads();
    }

#pragma unroll
    for (int hr = 0; hr < 2; hr++) {
        int row = wid * 16 + (lane >> 2) + hr * 8;
#pragma unroll
        for (int nt = 0; nt < 4; nt++) {
            int col = nt * 8 + (lane & 3) * 2;
            float o0 = acc[nt][hr * 2 + 0] + b2[col];
            float o1 = acc[nt][hr * 2 + 1] + b2[col + 1];
            *(float2*)&out[((size_t)b * NN + n0 + row) * PP + col] = make_float2(o0, o1);
        }
    }
}

// ---------------- launch -----------------------------------------------------------
extern "C" void kernel_launch(void* const* d_in, const int* in_sizes, int n_in,
                              void* d_out, int out_size) {
    (void)in_sizes; (void)n_in; (void)out_size;
    const float* node_feats = (const float*)d_in[0];
    const float* z          = (const float*)d_in[1];
    const int*   children   = (const int*)  d_in[2];
    const float* conv1_w    = (const float*)d_in[3];
    const float* conv1_b    = (const float*)d_in[4];
    const float* conv2_w    = (const float*)d_in[5];
    const float* conv2_b    = (const float*)d_in[6];
    const float* mlp_w1     = (const float*)d_in[7];
    const float* mlp_b1     = (const float*)d_in[8];
    const float* mlp_w2     = (const float*)d_in[9];
    const float* mlp_b2     = (const float*)d_in[10];
    float* out = (float*)d_out;

    static bool attr_done = false;
    if (!attr_done) {
        cudaFuncSetAttribute(k_gemm<0>, cudaFuncAttributeMaxDynamicSharedMemorySize, GB_SMEM);
        cudaFuncSetAttribute(k_gemm<1>, cudaFuncAttributeMaxDynamicSharedMemorySize, GB_SMEM);
        cudaFuncSetAttribute(k_gemm<2>, cudaFuncAttributeMaxDynamicSharedMemorySize, GB_SMEM);
        cudaFuncSetAttribute(k_mlp2,    cudaFuncAttributeMaxDynamicSharedMemorySize, M2_SMEM);
        attr_done = true;
    }

    k_init<<<64, 256>>>();
    k_transpose<<<dim3(NN / 32, CC / 32, BB), dim3(32, 32)>>>(node_feats);
    k_pack<<<256, 256>>>(conv1_w, conv2_w, mlp_w1, mlp_w2);

    k_gemm<0><<<dim3(16, 2, BB), 256, GB_SMEM>>>(conv1_b, children, z);
    k_finalize<<<1, 64>>>(0);
    k_gemm<1><<<dim3(16, 2, BB), 256, GB_SMEM>>>(conv2_b, children, z);
    k_finalize<<<1, 64>>>(1);
    k_gemm<2><<<dim3(16, 2, BB), 256, GB_SMEM>>>(mlp_b1, children, z);

    k_mlp2<<<dim3(16, BB), 256, M2_SMEM>>>(mlp_b2, out);
}